// round 13
// baseline (speedup 1.0000x reference)
#include <cuda_runtime.h>
#include <cuda_bf16.h>
#include <math.h>
#include <cstdint>

#define FULLMASK 0xffffffffu
typedef unsigned long long u64;

static constexpr int NL     = 2048;
static constexpr int NQ     = 16384;
static constexpr int NB     = 2;
static constexpr int H      = 64;
static constexpr int PH     = 256;
static constexpr int COUT   = 3;
static constexpr int KCAP   = 32;
static constexpr int CAP    = 160;
static constexpr int THREADS= 128;
static constexpr int WARPS  = 4;
static constexpr int NBLOCK = 592;   // 148 x 4 CTAs

// decoded scratch
__device__ float g_dec[NB * NQ * H];   // 8 MB

// ---- main-kernel SMEM byte offsets ----
static constexpr int OFF_FRAGB = 0;       // 4 arrays x 1024 u64 = 32768
static constexpr int OFF_CAND  = 32768;   // 4 warps x 160 u64   = 5120
static constexpr int OFF_WE0   = 37888;   // 256 f32
static constexpr int OFF_BE0   = 38912;   // 64 f32
static constexpr int OFF_BE1   = 39168;   // 64 f32
static constexpr int OFF_BE2   = 39424;   // 64 f32
static constexpr int OFF_WSW0  = 39680;   // 32 f32
static constexpr int OFF_BSW0  = 39808;   // 16 f32
static constexpr int OFF_WSW1  = 39872;   // 32 f32
static constexpr int OFF_BSW1  = 40000;   // 2 f32
static constexpr int SMEM_BYTES= 40064;   // x4 CTAs = 160KB; L1D carveout ~67KB

// ---------- helpers ----------
__device__ __forceinline__ uint32_t pkbf(float lo, float hi) {
    uint32_t r; asm("cvt.rn.bf16x2.f32 %0, %1, %2;" : "=r"(r) : "f"(hi), "f"(lo)); return r;
}
__device__ __forceinline__ float lof(float x) {
    return x - __bfloat162float(__float2bfloat16(x));
}
__device__ __forceinline__ void hmma(float c[4], const uint32_t a[4], uint32_t b0, uint32_t b1) {
    asm volatile("mma.sync.aligned.m16n8k16.row.col.f32.bf16.bf16.f32 "
        "{%0,%1,%2,%3}, {%4,%5,%6,%7}, {%8,%9}, {%0,%1,%2,%3};"
        : "+f"(c[0]), "+f"(c[1]), "+f"(c[2]), "+f"(c[3])
        : "r"(a[0]), "r"(a[1]), "r"(a[2]), "r"(a[3]), "r"(b0), "r"(b1));
}
__device__ __forceinline__ u64 pk2(float a, float b) {
    u64 r; asm("mov.b64 %0,{%1,%2};" : "=l"(r) : "f"(a), "f"(b)); return r;
}
__device__ __forceinline__ void upk2(u64 v, float& a, float& b) {
    asm("mov.b64 {%0,%1},%2;" : "=f"(a), "=f"(b) : "l"(v));
}
__device__ __forceinline__ u64 f2fma(u64 a, u64 b, u64 c) {
    u64 d; asm("fma.rn.f32x2 %0,%1,%2,%3;" : "=l"(d) : "l"(a), "l"(b), "l"(c)); return d;
}
__device__ __forceinline__ u64 f2add(u64 a, u64 b) {
    u64 d; asm("add.rn.f32x2 %0,%1,%2;" : "=l"(d) : "l"(a), "l"(b)); return d;
}
__device__ __forceinline__ unsigned redux_min_u32(unsigned v) {
    unsigned r; asm("redux.sync.min.u32 %0, %1, 0xffffffff;" : "=r"(r) : "r"(v)); return r;
}
__device__ __forceinline__ float gelu_f(float x) {
    float z = fabsf(x) * 0.7071067811865476f;
    float t = __fdividef(1.0f, fmaf(0.3275911f, z, 1.0f));
    float p = t * fmaf(t, fmaf(t, fmaf(t, fmaf(t, 1.061405429f, -1.453152027f),
                                        1.421413741f), -0.284496736f), 0.254829592f);
    float e = __expf(-z * z);
    float er = fmaf(-p, e, 1.0f);
    er = copysignf(er, x);
    return 0.5f * x * (1.0f + er);
}
__device__ __forceinline__ void ce(u64& a, u64& b) {
    u64 lo = a < b ? a : b;
    u64 hi = a < b ? b : a;
    a = lo; b = hi;
}

__global__ void __launch_bounds__(THREADS, 4)
magno_kernel(const float* __restrict__ lat,  const float* __restrict__ rnd,
             const float* __restrict__ qry,
             const float* __restrict__ we0,  const float* __restrict__ be0,
             const float* __restrict__ we1,  const float* __restrict__ be1,
             const float* __restrict__ we2,  const float* __restrict__ be2,
             const float* __restrict__ wsw0, const float* __restrict__ bsw0,
             const float* __restrict__ wsw1, const float* __restrict__ bsw1)
{
    extern __shared__ char smem[];
    const int tid = threadIdx.x, warp = tid >> 5, lane = tid & 31;
    const int gr = lane >> 2, qd = lane & 3;

    // ---- B fragments: 0=W1hi 1=W1lo 2=W2hi 3=W2lo ----
    {
        u64* fbw = (u64*)(smem + OFF_FRAGB);
        for (int i = tid; i < 4096; i += THREADS) {
            int arr = i >> 10, rem = i & 1023;
            int frag = rem >> 5, l = rem & 31;
            int kt = frag >> 3, nt = frag & 7;
            int k0 = kt*16 + 2*(l & 3);
            int n  = nt*8 + (l >> 2);
            const float* W = (arr < 2) ? we1 : we2;
            float w00 = W[(k0  )*H + n], w01 = W[(k0+1)*H + n];
            float w10 = W[(k0+8)*H + n], w11 = W[(k0+9)*H + n];
            if (arr & 1) { w00 = lof(w00); w01 = lof(w01); w10 = lof(w10); w11 = lof(w11); }
            fbw[i] = (u64)pkbf(w00, w01) | ((u64)pkbf(w10, w11) << 32);
        }
    }
    {
        float* f = (float*)smem;
        for (int t = tid; t < 4*H; t += THREADS) f[OFF_WE0/4 + t] = we0[t];
        for (int t = tid; t < H;   t += THREADS) {
            f[OFF_BE0/4 + t] = be0[t];
            f[OFF_BE1/4 + t] = be1[t];
            f[OFF_BE2/4 + t] = be2[t];
        }
        if (tid < 32)              f[OFF_WSW0/4 + tid]    = wsw0[tid];
        if (tid < 16)              f[OFF_BSW0/4 + tid]    = bsw0[tid];
        if (tid >= 32 && tid < 64) f[OFF_WSW1/4 + tid-32] = wsw1[tid-32];
        if (tid >= 64 && tid < 66) f[OFF_BSW1/4 + tid-64] = bsw1[tid-64];
    }
    __syncthreads();

    u64* cand = (u64*)(smem + OFF_CAND) + warp * CAP;
    const u64* fb = (const u64*)(smem + OFF_FRAGB);
    const float2* latf2 = (const float2*)lat;
    const float* smf = (const float*)smem;

    const float R0SQ = (float)(0.055 * 0.055);
    const float R1SQ = (float)(0.11  * 0.11);
    const unsigned lt_mask = (1u << lane) - 1u;

    for (int q = blockIdx.x * WARPS + warp; q < NB * NQ; q += gridDim.x * WARPS) {
        const int  bix = q >> 14;
        const float qx = qry[2*q], qy = qry[2*q+1];

        // ---- scale-mixing weights ----
        float s0 = smf[OFF_BSW1/4+0], s1 = smf[OFF_BSW1/4+1];
#pragma unroll
        for (int t = 0; t < 16; t++) {
            float z = smf[OFF_BSW0/4+t] + qx*smf[OFF_WSW0/4+t] + qy*smf[OFF_WSW0/4+16+t];
            z = fmaxf(z, 0.0f);
            s0 = fmaf(z, smf[OFF_WSW1/4+2*t+0], s0);
            s1 = fmaf(z, smf[OFF_WSW1/4+2*t+1], s1);
        }
        float mx = fmaxf(s0, s1);
        float e0 = __expf(s0 - mx), e1 = __expf(s1 - mx);
        float inv = __fdividef(1.0f, e0 + e1);
        float sw0v = e0 * inv, sw1v = e1 * inv;

        // ---- candidate collection ----
        int cnt = 0;
        for (int l = lane; l < NL; l += 32) {
            float2 y = __ldg(latf2 + l);
            float dx = qx - y.x, dy = qy - y.y;
            float d2 = __fadd_rn(__fmul_rn(dx, dx), __fmul_rn(dy, dy));
            bool pr = d2 <= R1SQ;
            unsigned m = __ballot_sync(FULLMASK, pr);
            if (pr) {
                int pos = cnt + __popc(m & lt_mask);
                if (pos < CAP)
                    cand[pos] = ((u64)__float_as_uint(d2) << 32) | (unsigned)l;
            }
            cnt += __popc(m);
        }
        if (cnt > CAP) cnt = CAP;
        __syncwarp();

        // ---- exact K=32 selection ----
        u64 mykey = 0x7f7fffff00000000ull;
        int nsel;
        if (cnt <= KCAP) {
            nsel = cnt;
            if (lane < cnt) mykey = cand[lane];
        } else {
            nsel = KCAP;
            u64 c0, c1, c2, c3, c4, c5;
            c0 = (lane       < cnt) ? cand[lane      ] : ~0ull;
            c1 = (lane + 32  < cnt) ? cand[lane + 32 ] : ~0ull;
            c2 = (lane + 64  < cnt) ? cand[lane + 64 ] : ~0ull;
            c3 = (lane + 96  < cnt) ? cand[lane + 96 ] : ~0ull;
            c4 = (lane + 128 < cnt) ? cand[lane + 128] : ~0ull;
            c5 = ~0ull;
            ce(c0,c1); ce(c2,c3); ce(c4,c5);
            ce(c0,c2); ce(c3,c5); ce(c1,c4);
            ce(c0,c1); ce(c2,c3); ce(c4,c5);
            ce(c1,c2); ce(c3,c4); ce(c2,c3);
            unsigned hdb = (unsigned)(c0 >> 32);
#pragma unroll 1
            for (int r = 0; r < KCAP; r++) {
                unsigned m = redux_min_u32(hdb);
                unsigned tied = __ballot_sync(FULLMASK, hdb == m);
                int src;
                if ((tied & (tied - 1u)) == 0u) {
                    src = __ffs(tied) - 1;
                } else {
                    unsigned lw = (hdb == m) ? (unsigned)c0 : 0xffffffffu;
                    unsigned mi = redux_min_u32(lw);
                    src = __ffs(__ballot_sync(FULLMASK, lw == mi)) - 1;
                }
                u64 win = __shfl_sync(FULLMASK, c0, src);
                if (lane == r) mykey = win;
                bool pop = (lane == src);
                c0 = pop ? c1 : c0; c1 = pop ? c2 : c1; c2 = pop ? c3 : c2;
                c3 = pop ? c4 : c3; c4 = pop ? c5 : c4; c5 = pop ? ~0ull : c5;
                hdb = (unsigned)(c0 >> 32);
            }
        }
        float seld2  = __uint_as_float((unsigned)(mykey >> 32));
        int   selidx = (int)(mykey & 0xffffffffu);
        if (lane >= nsel) { seld2 = 3.4e38f; selidx = 0; }

        bool v0 = (lane < nsel) && (seld2 <= R0SQ);
        int  c0cnt = __popc(__ballot_sync(FULLMASK, v0));
        float coeff = 0.0f;
        if (v0)          coeff += sw0v / (float)(c0cnt > 1 ? c0cnt : 1);
        if (lane < nsel) coeff += sw1v / (float)(nsel  > 1 ? nsel  : 1);

        {
            const float* frowf = rnd + (size_t)(bix * NL + selidx) * H;
            asm volatile("prefetch.global.L1 [%0];" :: "l"(frowf));
            asm volatile("prefetch.global.L1 [%0];" :: "l"(frowf + 32));
        }

        // ---- per-lane fragment rows: rr = mt*2 + hf -> row = mt*16 + hf*8 + gr ----
        int   rsi[4];
        float cfr[4];
#pragma unroll
        for (int rr = 0; rr < 4; rr++) {
            int r = (rr >> 1)*16 + (rr & 1)*8 + gr;
            rsi[rr] = __shfl_sync(FULLMASK, selidx, r);
            cfr[rr] = __shfl_sync(FULLMASK, coeff,  r);
        }

        // ---- layer 0 directly into A fragments (no staging) ----
        uint32_t Ahi[2][4][4], Alo[2][4][4];
        {
            u64 yx2[4], yy2[4];
#pragma unroll
            for (int rr = 0; rr < 4; rr++) {
                float2 yc = __ldg(latf2 + rsi[rr]);
                yx2[rr] = pk2(yc.x, yc.x);
                yy2[rr] = pk2(yc.y, yc.y);
            }
            u64 qx2 = pk2(qx, qx), qy2 = pk2(qy, qy);
            const u64* w0r0 = (const u64*)(smem + OFF_WE0);
            const u64* w0r1 = (const u64*)(smem + OFF_WE0 + 256);
            const u64* w0r2 = (const u64*)(smem + OFF_WE0 + 512);
            const u64* w0r3 = (const u64*)(smem + OFF_WE0 + 768);
            const u64* b0p  = (const u64*)(smem + OFF_BE0);
#pragma unroll
            for (int kt = 0; kt < 4; kt++) {
                int p0 = kt*8 + qd, p1 = p0 + 4;
                u64 A0 = w0r0[p0], A1 = w0r1[p0];
                u64 D0 = w0r0[p1], D1 = w0r1[p1];
                u64 Q0 = f2fma(qy2, w0r3[p0], f2fma(qx2, w0r2[p0], b0p[p0]));
                u64 Q1 = f2fma(qy2, w0r3[p1], f2fma(qx2, w0r2[p1], b0p[p1]));
#pragma unroll
                for (int rr = 0; rr < 4; rr++) {
                    int mt = rr >> 1, s = rr & 1;
                    u64 t0 = f2fma(yx2[rr], A0, f2fma(yy2[rr], A1, Q0));
                    u64 t1 = f2fma(yx2[rr], D0, f2fma(yy2[rr], D1, Q1));
                    float a, b, c, d;
                    upk2(t0, a, b); upk2(t1, c, d);
                    float g0 = gelu_f(a), g1 = gelu_f(b);
                    float g2 = gelu_f(c), g3 = gelu_f(d);
                    Ahi[mt][kt][s]   = pkbf(g0, g1);
                    Ahi[mt][kt][2+s] = pkbf(g2, g3);
                    Alo[mt][kt][s]   = pkbf(lof(g0), lof(g1));
                    Alo[mt][kt][2+s] = pkbf(lof(g2), lof(g3));
                }
            }
        }

        // ---- layer 1 (nt-outer, fused bias+gelu+re-fragment) ----
        uint32_t A2hi[2][4][4], A2lo[2][4][4];
        {
            const float2* b1p = (const float2*)(smem + OFF_BE1);
#pragma unroll
            for (int nt = 0; nt < 8; nt++) {
                float ac0[4] = {0,0,0,0}, ac1[4] = {0,0,0,0};
#pragma unroll
                for (int kt = 0; kt < 4; kt++) {
                    u64 bh = fb[0*1024 + (kt*8+nt)*32 + lane];
                    u64 bl = fb[1*1024 + (kt*8+nt)*32 + lane];
                    hmma(ac0, Ahi[0][kt], (uint32_t)bh, (uint32_t)(bh >> 32));
                    hmma(ac1, Ahi[1][kt], (uint32_t)bh, (uint32_t)(bh >> 32));
                    hmma(ac0, Alo[0][kt], (uint32_t)bh, (uint32_t)(bh >> 32));
                    hmma(ac1, Alo[1][kt], (uint32_t)bh, (uint32_t)(bh >> 32));
                    hmma(ac0, Ahi[0][kt], (uint32_t)bl, (uint32_t)(bl >> 32));
                    hmma(ac1, Ahi[1][kt], (uint32_t)bl, (uint32_t)(bl >> 32));
                }
                float2 bb = b1p[nt*4 + qd];
                int j = nt >> 1, s2 = nt & 1;
                {
                    float g0 = gelu_f(ac0[0] + bb.x), g1 = gelu_f(ac0[1] + bb.y);
                    float g2 = gelu_f(ac0[2] + bb.x), g3 = gelu_f(ac0[3] + bb.y);
                    A2hi[0][j][2*s2]   = pkbf(g0, g1);
                    A2hi[0][j][2*s2+1] = pkbf(g2, g3);
                    A2lo[0][j][2*s2]   = pkbf(lof(g0), lof(g1));
                    A2lo[0][j][2*s2+1] = pkbf(lof(g2), lof(g3));
                }
                {
                    float g0 = gelu_f(ac1[0] + bb.x), g1 = gelu_f(ac1[1] + bb.y);
                    float g2 = gelu_f(ac1[2] + bb.x), g3 = gelu_f(ac1[3] + bb.y);
                    A2hi[1][j][2*s2]   = pkbf(g0, g1);
                    A2hi[1][j][2*s2+1] = pkbf(g2, g3);
                    A2lo[1][j][2*s2]   = pkbf(lof(g0), lof(g1));
                    A2lo[1][j][2*s2+1] = pkbf(lof(g2), lof(g3));
                }
            }
        }

        // ---- layer 2 + epilogue (nt-outer, fused) ----
        u64 myd = 0;
        {
            const float2* b2p = (const float2*)(smem + OFF_BE2);
            const float* rb = rnd + (size_t)bix * NL * H;
            const int colb = 2*qd;
#pragma unroll
            for (int nt = 0; nt < 8; nt++) {
                float ac0[4] = {0,0,0,0}, ac1[4] = {0,0,0,0};
#pragma unroll
                for (int kt = 0; kt < 4; kt++) {
                    u64 bh = fb[2*1024 + (kt*8+nt)*32 + lane];
                    u64 bl = fb[3*1024 + (kt*8+nt)*32 + lane];
                    hmma(ac0, A2hi[0][kt], (uint32_t)bh, (uint32_t)(bh >> 32));
                    hmma(ac1, A2hi[1][kt], (uint32_t)bh, (uint32_t)(bh >> 32));
                    hmma(ac0, A2lo[0][kt], (uint32_t)bh, (uint32_t)(bh >> 32));
                    hmma(ac1, A2lo[1][kt], (uint32_t)bh, (uint32_t)(bh >> 32));
                    hmma(ac0, A2hi[0][kt], (uint32_t)bl, (uint32_t)(bl >> 32));
                    hmma(ac1, A2hi[1][kt], (uint32_t)bl, (uint32_t)(bl >> 32));
                }
                float2 bb = b2p[nt*4 + qd];
                float sx = 0.f, sy = 0.f;
#pragma unroll
                for (int rr = 0; rr < 4; rr++) {
                    int mt = rr >> 1, hf = rr & 1;
                    float2 fy = __ldg((const float2*)(rb + (size_t)rsi[rr]*H + nt*8 + colb));
                    float cfv = cfr[rr];
                    float* ac = mt ? ac1 : ac0;
                    sx += (ac[2*hf+0] + bb.x) * fy.x * cfv;
                    sy += (ac[2*hf+1] + bb.y) * fy.y * cfv;
                }
                u64 v = pk2(sx, sy);
                v = f2add(v, __shfl_xor_sync(FULLMASK, v, 4));
                v = f2add(v, __shfl_xor_sync(FULLMASK, v, 8));
                v = f2add(v, __shfl_xor_sync(FULLMASK, v, 16));
                if ((lane >> 2) == nt) myd = v;
            }
        }
        ((u64*)g_dec)[(size_t)q * 32 + lane] = myd;
    }
}

// ======== zero-init for atomic projection output ========
__global__ void zero_out_kernel(float* __restrict__ out) {
    int i = blockIdx.x * 256 + threadIdx.x;
    if (i < NB * NQ * COUT) out[i] = 0.0f;
}

// ======== projection kernel: split hidden dim across 2 blocks/row-batch ========
static constexpr int PTHREADS = 128;
static constexpr int PGRID    = 2 * NB * NQ / PTHREADS;   // 512
static constexpr int POFF_WP0 = 0;          // 8192 floats: wp0 half [64][128]
static constexpr int POFF_BP0 = 8192;       // 128
static constexpr int POFF_WP1 = 8320;       // 384: wp1 half [128][3]
static constexpr int POFF_BP1 = 8704;       // 3 (+1)
static constexpr int PSMEM_FLOATS = 8708;
static constexpr int PSMEM_BYTES  = PSMEM_FLOATS * 4;   // 34832 B -> ~6 CTAs/SM

__global__ void __launch_bounds__(PTHREADS)
proj_kernel(const float* __restrict__ wp0, const float* __restrict__ bp0,
            const float* __restrict__ wp1, const float* __restrict__ bp1,
            float* __restrict__ out)
{
    extern __shared__ float psm[];
    const int tid = threadIdx.x;
    const int hb  = blockIdx.x & 1;                 // hidden half
    const int row = (blockIdx.x >> 1) * PTHREADS + tid;

    for (int t = tid; t < H*128; t += PTHREADS) {
        int i = t >> 7, c = t & 127;
        psm[POFF_WP0 + t] = wp0[i*PH + hb*128 + c];
    }
    for (int t = tid; t < 128; t += PTHREADS) psm[POFF_BP0 + t] = bp0[hb*128 + t];
    for (int t = tid; t < 128*COUT; t += PTHREADS) psm[POFF_WP1 + t] = wp1[hb*128*COUT + t];
    if (tid < COUT) psm[POFF_BP1 + tid] = bp1[tid];
    __syncthreads();

    float dec[64];
    {
        const float4* dp = (const float4*)(g_dec + (size_t)row * H);
#pragma unroll
        for (int i = 0; i < 16; i++) {
            float4 v = dp[i];
            dec[4*i+0] = v.x; dec[4*i+1] = v.y;
            dec[4*i+2] = v.z; dec[4*i+3] = v.w;
        }
    }

    float o0 = hb ? 0.f : psm[POFF_BP1+0];
    float o1 = hb ? 0.f : psm[POFF_BP1+1];
    float o2 = hb ? 0.f : psm[POFF_BP1+2];

#pragma unroll 1
    for (int cc = 0; cc < 2; cc++) {              // 2 chunks of 64 local hidden
        u64 a[32];
        {
            const u64* bp = (const u64*)(psm + POFF_BP0 + cc * 64);
#pragma unroll
            for (int p = 0; p < 32; p++) a[p] = bp[p];
        }
#pragma unroll 4
        for (int i = 0; i < 64; i++) {
            u64 dd = pk2(dec[i], dec[i]);
            const ulonglong2* wr =
                (const ulonglong2*)(psm + POFF_WP0 + i*128 + cc*64);
#pragma unroll
            for (int j2 = 0; j2 < 16; j2++) {
                ulonglong2 w = wr[j2];            // warp-uniform LDS.128 broadcast
                a[2*j2]   = f2fma(dd, w.x, a[2*j2]);
                a[2*j2+1] = f2fma(dd, w.y, a[2*j2+1]);
            }
        }
#pragma unroll
        for (int p = 0; p < 32; p++) {
            float x, y; upk2(a[p], x, y);
            float g0 = gelu_f(x), g1 = gelu_f(y);
            int jj = cc * 64 + 2 * p;             // local hidden index
            o0 = fmaf(g0, psm[POFF_WP1 + jj*3 + 0], o0);
            o1 = fmaf(g0, psm[POFF_WP1 + jj*3 + 1], o1);
            o2 = fmaf(g0, psm[POFF_WP1 + jj*3 + 2], o2);
            o0 = fmaf(g1, psm[POFF_WP1 + jj*3 + 3], o0);
            o1 = fmaf(g1, psm[POFF_WP1 + jj*3 + 4], o1);
            o2 = fmaf(g1, psm[POFF_WP1 + jj*3 + 5], o2);
        }
    }

    atomicAdd(out + row*3 + 0, o0);
    atomicAdd(out + row*3 + 1, o1);
    atomicAdd(out + row*3 + 2, o2);
}

extern "C" void kernel_launch(void* const* d_in, const int* in_sizes, int n_in,
                              void* d_out, int out_size) {
    const float* lat  = (const float*)d_in[0];
    const float* rnd  = (const float*)d_in[1];
    const float* qry  = (const float*)d_in[2];
    const float* we0  = (const float*)d_in[3];
    const float* be0  = (const float*)d_in[4];
    const float* we1  = (const float*)d_in[5];
    const float* be1  = (const float*)d_in[6];
    const float* we2  = (const float*)d_in[7];
    const float* be2  = (const float*)d_in[8];
    const float* wsw0 = (const float*)d_in[9];
    const float* bsw0 = (const float*)d_in[10];
    const float* wsw1 = (const float*)d_in[11];
    const float* bsw1 = (const float*)d_in[12];
    const float* wp0  = (const float*)d_in[13];
    const float* bp0  = (const float*)d_in[14];
    const float* wp1  = (const float*)d_in[15];
    const float* bp1  = (const float*)d_in[16];
    float* out = (float*)d_out;

    cudaFuncSetAttribute(magno_kernel, cudaFuncAttributeMaxDynamicSharedMemorySize, SMEM_BYTES);
    cudaFuncSetAttribute(proj_kernel,  cudaFuncAttributeMaxDynamicSharedMemorySize, PSMEM_BYTES);
    zero_out_kernel<<<(NB*NQ*COUT + 255)/256, 256>>>(out);
    magno_kernel<<<NBLOCK, THREADS, SMEM_BYTES>>>(
        lat, rnd, qry, we0, be0, we1, be1, we2, be2,
        wsw0, bsw0, wsw1, bsw1);
    proj_kernel<<<PGRID, PTHREADS, PSMEM_BYTES>>>(wp0, bp0, wp1, bp1, out);
}

// round 14
// speedup vs baseline: 1.2375x; 1.2375x over previous
#include <cuda_runtime.h>
#include <cuda_bf16.h>
#include <math.h>
#include <cstdint>

#define FULLMASK 0xffffffffu
typedef unsigned long long u64;

static constexpr int NL     = 2048;
static constexpr int NQ     = 16384;
static constexpr int NB     = 2;
static constexpr int H      = 64;
static constexpr int PH     = 256;
static constexpr int COUT   = 3;
static constexpr int KCAP   = 32;
static constexpr int CAP    = 160;
static constexpr int THREADS= 128;
static constexpr int WARPS  = 4;
static constexpr int NBLOCK = 444;   // 148 SMs x 3 CTAs

// decoded scratch
__device__ float g_dec[NB * NQ * H];   // 8 MB

// ---- main-kernel SMEM byte offsets (R12 layout) ----
static constexpr int OFF_ASTG  = 0;       // 4 warps x 4096 (A staging, swizzled) = 16384
static constexpr int OFF_FRAGB = 16384;   // 4 arrays x 1024 u64 (B fragments)    = 32768
static constexpr int OFF_CAND  = 49152;   // 4 warps x 160 u64                    = 5120
static constexpr int OFF_WE0   = 54272;   // 256 f32 = 1024B
static constexpr int OFF_BE0   = 55296;   // 64 f32
static constexpr int OFF_BE1   = 55552;   // 64 f32
static constexpr int OFF_BE2   = 55808;   // 64 f32
static constexpr int OFF_WSW0  = 56064;   // 32 f32
static constexpr int OFF_BSW0  = 56192;   // 16 f32
static constexpr int OFF_WSW1  = 56256;   // 32 f32
static constexpr int OFF_BSW1  = 56384;   // 2 f32
static constexpr int SMEM_BYTES= 56576;   // x3 CTAs = 170KB; L1D carveout ~58KB

// ---------- helpers ----------
__device__ __forceinline__ uint32_t smem_to_u32(const void* p) {
    uint32_t a;
    asm("{ .reg .u64 t; cvta.to.shared.u64 t, %1; cvt.u32.u64 %0, t; }" : "=r"(a) : "l"(p));
    return a;
}
__device__ __forceinline__ uint32_t pkbf(float lo, float hi) {
    uint32_t r; asm("cvt.rn.bf16x2.f32 %0, %1, %2;" : "=r"(r) : "f"(hi), "f"(lo)); return r;
}
__device__ __forceinline__ float lof(float x) {
    return x - __bfloat162float(__float2bfloat16(x));
}
__device__ __forceinline__ void hmma(float c[4], const uint32_t a[4], uint32_t b0, uint32_t b1) {
    asm volatile("mma.sync.aligned.m16n8k16.row.col.f32.bf16.bf16.f32 "
        "{%0,%1,%2,%3}, {%4,%5,%6,%7}, {%8,%9}, {%0,%1,%2,%3};"
        : "+f"(c[0]), "+f"(c[1]), "+f"(c[2]), "+f"(c[3])
        : "r"(a[0]), "r"(a[1]), "r"(a[2]), "r"(a[3]), "r"(b0), "r"(b1));
}
__device__ __forceinline__ void ldsm4(uint32_t r[4], uint32_t addr) {
    asm volatile("ldmatrix.sync.aligned.m8n8.x4.shared.b16 {%0,%1,%2,%3}, [%4];"
        : "=r"(r[0]), "=r"(r[1]), "=r"(r[2]), "=r"(r[3]) : "r"(addr));
}
__device__ __forceinline__ u64 pk2(float a, float b) {
    u64 r; asm("mov.b64 %0,{%1,%2};" : "=l"(r) : "f"(a), "f"(b)); return r;
}
__device__ __forceinline__ void upk2(u64 v, float& a, float& b) {
    asm("mov.b64 {%0,%1},%2;" : "=f"(a), "=f"(b) : "l"(v));
}
__device__ __forceinline__ u64 f2fma(u64 a, u64 b, u64 c) {
    u64 d; asm("fma.rn.f32x2 %0,%1,%2,%3;" : "=l"(d) : "l"(a), "l"(b), "l"(c)); return d;
}
__device__ __forceinline__ u64 f2add(u64 a, u64 b) {
    u64 d; asm("add.rn.f32x2 %0,%1,%2;" : "=l"(d) : "l"(a), "l"(b)); return d;
}
__device__ __forceinline__ unsigned redux_min_u32(unsigned v) {
    unsigned r; asm("redux.sync.min.u32 %0, %1, 0xffffffff;" : "=r"(r) : "r"(v)); return r;
}
__device__ __forceinline__ float gelu_f(float x) {
    float z = fabsf(x) * 0.7071067811865476f;
    float t = __fdividef(1.0f, fmaf(0.3275911f, z, 1.0f));
    float p = t * fmaf(t, fmaf(t, fmaf(t, fmaf(t, 1.061405429f, -1.453152027f),
                                        1.421413741f), -0.284496736f), 0.254829592f);
    float e = __expf(-z * z);
    float er = fmaf(-p, e, 1.0f);
    er = copysignf(er, x);
    return 0.5f * x * (1.0f + er);
}
__device__ __forceinline__ void ce(u64& a, u64& b) {
    u64 lo = a < b ? a : b;
    u64 hi = a < b ? b : a;
    a = lo; b = hi;
}

__global__ void __launch_bounds__(THREADS, 3)
magno_kernel(const float* __restrict__ lat,  const float* __restrict__ rnd,
             const float* __restrict__ qry,
             const float* __restrict__ we0,  const float* __restrict__ be0,
             const float* __restrict__ we1,  const float* __restrict__ be1,
             const float* __restrict__ we2,  const float* __restrict__ be2,
             const float* __restrict__ wsw0, const float* __restrict__ bsw0,
             const float* __restrict__ wsw1, const float* __restrict__ bsw1)
{
    extern __shared__ char smem[];
    const uint32_t smem_base = smem_to_u32(smem);
    const int tid = threadIdx.x, warp = tid >> 5, lane = tid & 31;

    // ---- B fragments: arrays 0=W1hi 1=W1lo 2=W2hi 3=W2lo ----
    {
        u64* fbw = (u64*)(smem + OFF_FRAGB);
        for (int i = tid; i < 4096; i += THREADS) {
            int arr = i >> 10, rem = i & 1023;
            int frag = rem >> 5, l = rem & 31;
            int kt = frag >> 3, nt = frag & 7;
            int k0 = kt*16 + 2*(l & 3);
            int n  = nt*8 + (l >> 2);
            const float* W = (arr < 2) ? we1 : we2;
            float w00 = W[(k0  )*H + n], w01 = W[(k0+1)*H + n];
            float w10 = W[(k0+8)*H + n], w11 = W[(k0+9)*H + n];
            if (arr & 1) { w00 = lof(w00); w01 = lof(w01); w10 = lof(w10); w11 = lof(w11); }
            fbw[i] = (u64)pkbf(w00, w01) | ((u64)pkbf(w10, w11) << 32);
        }
    }
    {
        float* f = (float*)smem;
        for (int t = tid; t < 4*H; t += THREADS) f[OFF_WE0/4 + t] = we0[t];
        for (int t = tid; t < H;   t += THREADS) {
            f[OFF_BE0/4 + t] = be0[t];
            f[OFF_BE1/4 + t] = be1[t];
            f[OFF_BE2/4 + t] = be2[t];
        }
        if (tid < 32)              f[OFF_WSW0/4 + tid]    = wsw0[tid];
        if (tid < 16)              f[OFF_BSW0/4 + tid]    = bsw0[tid];
        if (tid >= 32 && tid < 64) f[OFF_WSW1/4 + tid-32] = wsw1[tid-32];
        if (tid >= 64 && tid < 66) f[OFF_BSW1/4 + tid-64] = bsw1[tid-64];
    }
    __syncthreads();

    u64* cand = (u64*)(smem + OFF_CAND) + warp * CAP;
    const u64* fb = (const u64*)(smem + OFF_FRAGB);
    const float2* latf2 = (const float2*)lat;
    const float* smf = (const float*)smem;
    char* astg = smem + OFF_ASTG + warp * 4096;
    const uint32_t astg_u32 = smem_base + OFF_ASTG + warp * 4096;

    const float R0SQ = (float)(0.055 * 0.055);
    const float R1SQ = (float)(0.11  * 0.11);
    const unsigned lt_mask = (1u << lane) - 1u;

    for (int q = blockIdx.x * WARPS + warp; q < NB * NQ; q += gridDim.x * WARPS) {
        const int  bix = q >> 14;
        const float qx = qry[2*q], qy = qry[2*q+1];

        // ---- scale-mixing weights ----
        float s0 = smf[OFF_BSW1/4+0], s1 = smf[OFF_BSW1/4+1];
#pragma unroll
        for (int t = 0; t < 16; t++) {
            float z = smf[OFF_BSW0/4+t] + qx*smf[OFF_WSW0/4+t] + qy*smf[OFF_WSW0/4+16+t];
            z = fmaxf(z, 0.0f);
            s0 = fmaf(z, smf[OFF_WSW1/4+2*t+0], s0);
            s1 = fmaf(z, smf[OFF_WSW1/4+2*t+1], s1);
        }
        float mx = fmaxf(s0, s1);
        float e0 = __expf(s0 - mx), e1 = __expf(s1 - mx);
        float inv = __fdividef(1.0f, e0 + e1);
        float sw0v = e0 * inv, sw1v = e1 * inv;

        // ---- candidate collection ----
        int cnt = 0;
        for (int l = lane; l < NL; l += 32) {
            float2 y = __ldg(latf2 + l);
            float dx = qx - y.x, dy = qy - y.y;
            float d2 = __fadd_rn(__fmul_rn(dx, dx), __fmul_rn(dy, dy));
            bool pr = d2 <= R1SQ;
            unsigned m = __ballot_sync(FULLMASK, pr);
            if (pr) {
                int pos = cnt + __popc(m & lt_mask);
                if (pos < CAP)
                    cand[pos] = ((u64)__float_as_uint(d2) << 32) | (unsigned)l;
            }
            cnt += __popc(m);
        }
        if (cnt > CAP) cnt = CAP;
        __syncwarp();

        // ---- exact K=32 selection ----
        u64 mykey = 0x7f7fffff00000000ull;
        int nsel;
        if (cnt <= KCAP) {
            nsel = cnt;
            if (lane < cnt) mykey = cand[lane];
        } else {
            nsel = KCAP;
            u64 c0, c1, c2, c3, c4, c5;
            c0 = (lane       < cnt) ? cand[lane      ] : ~0ull;
            c1 = (lane + 32  < cnt) ? cand[lane + 32 ] : ~0ull;
            c2 = (lane + 64  < cnt) ? cand[lane + 64 ] : ~0ull;
            c3 = (lane + 96  < cnt) ? cand[lane + 96 ] : ~0ull;
            c4 = (lane + 128 < cnt) ? cand[lane + 128] : ~0ull;
            c5 = ~0ull;
            ce(c0,c1); ce(c2,c3); ce(c4,c5);
            ce(c0,c2); ce(c3,c5); ce(c1,c4);
            ce(c0,c1); ce(c2,c3); ce(c4,c5);
            ce(c1,c2); ce(c3,c4); ce(c2,c3);
            unsigned hdb = (unsigned)(c0 >> 32);
#pragma unroll 1
            for (int r = 0; r < KCAP; r++) {
                unsigned m = redux_min_u32(hdb);
                unsigned tied = __ballot_sync(FULLMASK, hdb == m);
                int src;
                if ((tied & (tied - 1u)) == 0u) {
                    src = __ffs(tied) - 1;
                } else {
                    unsigned lw = (hdb == m) ? (unsigned)c0 : 0xffffffffu;
                    unsigned mi = redux_min_u32(lw);
                    src = __ffs(__ballot_sync(FULLMASK, lw == mi)) - 1;
                }
                u64 win = __shfl_sync(FULLMASK, c0, src);
                if (lane == r) mykey = win;
                bool pop = (lane == src);
                c0 = pop ? c1 : c0; c1 = pop ? c2 : c1; c2 = pop ? c3 : c2;
                c3 = pop ? c4 : c3; c4 = pop ? c5 : c4; c5 = pop ? ~0ull : c5;
                hdb = (unsigned)(c0 >> 32);
            }
        }
        float seld2  = __uint_as_float((unsigned)(mykey >> 32));
        int   selidx = (int)(mykey & 0xffffffffu);
        if (lane >= nsel) { seld2 = 3.4e38f; selidx = 0; }

        bool v0 = (lane < nsel) && (seld2 <= R0SQ);
        int  c0cnt = __popc(__ballot_sync(FULLMASK, v0));
        float coeff = 0.0f;
        if (v0)          coeff += sw0v / (float)(c0cnt > 1 ? c0cnt : 1);
        if (lane < nsel) coeff += sw1v / (float)(nsel  > 1 ? nsel  : 1);

        {
            const float* frowf = rnd + (size_t)(bix * NL + selidx) * H;
            asm volatile("prefetch.global.L1 [%0];" :: "l"(frowf));
            asm volatile("prefetch.global.L1 [%0];" :: "l"(frowf + 32));
        }

        // ---- layer 0 (lane = neighbor row), pack bf16 hi/lo ----
        uint32_t hiP[32], loP[32];
        {
            float2 yc = __ldg(latf2 + selidx);
            u64 yx2 = pk2(yc.x, yc.x), yy2 = pk2(yc.y, yc.y);
            u64 qx2 = pk2(qx, qx),     qy2 = pk2(qy, qy);
            const u64* w0r0 = (const u64*)(smem + OFF_WE0);
            const u64* w0r1 = (const u64*)(smem + OFF_WE0 + 256);
            const u64* w0r2 = (const u64*)(smem + OFF_WE0 + 512);
            const u64* w0r3 = (const u64*)(smem + OFF_WE0 + 768);
            const u64* b0p  = (const u64*)(smem + OFF_BE0);
#pragma unroll
            for (int jp = 0; jp < 32; jp++) {
                u64 t = b0p[jp];
                t = f2fma(yx2, w0r0[jp], t);
                t = f2fma(yy2, w0r1[jp], t);
                t = f2fma(qx2, w0r2[jp], t);
                t = f2fma(qy2, w0r3[jp], t);
                float a, b; upk2(t, a, b);
                float g0 = gelu_f(a), g1 = gelu_f(b);
                hiP[jp] = pkbf(g0, g1);
                loP[jp] = pkbf(lof(g0), lof(g1));
            }
        }

        // ---- stage hi/lo, ldmatrix A fragments ----
        uint32_t Ahi[2][4][4], Alo[2][4][4];
        __syncwarp();
#pragma unroll
        for (int c = 0; c < 8; c++) {
            uint32_t off = (uint32_t)(lane*128 + ((c ^ (lane & 7)) << 4));
            *(uint4*)(astg + off) = make_uint4(hiP[4*c], hiP[4*c+1], hiP[4*c+2], hiP[4*c+3]);
        }
        __syncwarp();
#pragma unroll
        for (int mt = 0; mt < 2; mt++)
#pragma unroll
            for (int kt = 0; kt < 4; kt++) {
                int row = mt*16 + (lane & 15);
                int chunk = 2*kt + (lane >> 4);
                ldsm4(Ahi[mt][kt], astg_u32 + row*128 + ((chunk ^ (row & 7)) << 4));
            }
        __syncwarp();
#pragma unroll
        for (int c = 0; c < 8; c++) {
            uint32_t off = (uint32_t)(lane*128 + ((c ^ (lane & 7)) << 4));
            *(uint4*)(astg + off) = make_uint4(loP[4*c], loP[4*c+1], loP[4*c+2], loP[4*c+3]);
        }
        __syncwarp();
#pragma unroll
        for (int mt = 0; mt < 2; mt++)
#pragma unroll
            for (int kt = 0; kt < 4; kt++) {
                int row = mt*16 + (lane & 15);
                int chunk = 2*kt + (lane >> 4);
                ldsm4(Alo[mt][kt], astg_u32 + row*128 + ((chunk ^ (row & 7)) << 4));
            }

        // ---- layer 1: acc = Ahi*W1hi + Alo*W1hi + Ahi*W1lo ----
        float acc[2][8][4];
#pragma unroll
        for (int mt = 0; mt < 2; mt++)
#pragma unroll
            for (int nt = 0; nt < 8; nt++)
#pragma unroll
                for (int r = 0; r < 4; r++) acc[mt][nt][r] = 0.0f;

#define PASS(AREG, ARR) \
        _Pragma("unroll") \
        for (int kt = 0; kt < 4; kt++) { \
            u64 bf[8]; \
            _Pragma("unroll") \
            for (int nt = 0; nt < 8; nt++) bf[nt] = fb[(ARR)*1024 + (kt*8+nt)*32 + lane]; \
            _Pragma("unroll") \
            for (int mt = 0; mt < 2; mt++) \
            _Pragma("unroll") \
            for (int nt = 0; nt < 8; nt++) \
                hmma(acc[mt][nt], AREG[mt][kt], (uint32_t)bf[nt], (uint32_t)(bf[nt] >> 32)); \
        }

        PASS(Ahi, 0)
        PASS(Alo, 0)
        PASS(Ahi, 1)

        // ---- bias + gelu + re-fragment (C-frag -> A-frag, register-exact) ----
        uint32_t A2hi[2][4][4], A2lo[2][4][4];
        {
            const float2* b1p = (const float2*)(smem + OFF_BE1);
#pragma unroll
            for (int mt = 0; mt < 2; mt++)
#pragma unroll
                for (int j = 0; j < 4; j++)
#pragma unroll
                    for (int s = 0; s < 2; s++) {
                        int nt = 2*j + s;
                        float2 bb = b1p[nt*4 + (lane & 3)];
                        float g0 = gelu_f(acc[mt][nt][0] + bb.x);
                        float g1 = gelu_f(acc[mt][nt][1] + bb.y);
                        float g2 = gelu_f(acc[mt][nt][2] + bb.x);
                        float g3 = gelu_f(acc[mt][nt][3] + bb.y);
                        A2hi[mt][j][2*s]   = pkbf(g0, g1);
                        A2hi[mt][j][2*s+1] = pkbf(g2, g3);
                        A2lo[mt][j][2*s]   = pkbf(lof(g0), lof(g1));
                        A2lo[mt][j][2*s+1] = pkbf(lof(g2), lof(g3));
                    }
        }

        // ---- layer 2 ----
#pragma unroll
        for (int mt = 0; mt < 2; mt++)
#pragma unroll
            for (int nt = 0; nt < 8; nt++)
#pragma unroll
                for (int r = 0; r < 4; r++) acc[mt][nt][r] = 0.0f;

        PASS(A2hi, 2)
        PASS(A2lo, 2)
        PASS(A2hi, 3)
#undef PASS

        // ---- epilogue in fragment layout ----
        {
            float cf[2][2]; int si[2][2];
#pragma unroll
            for (int mt = 0; mt < 2; mt++)
#pragma unroll
                for (int hf = 0; hf < 2; hf++) {
                    int src = mt*16 + (lane >> 2) + 8*hf;
                    cf[mt][hf] = __shfl_sync(FULLMASK, coeff,  src);
                    si[mt][hf] = __shfl_sync(FULLMASK, selidx, src);
                }
            const float* rb = rnd + (size_t)bix * NL * H;
            const float2* b2p = (const float2*)(smem + OFF_BE2);
            u64 red[8];
#pragma unroll
            for (int nt = 0; nt < 8; nt++) {
                float2 bb = b2p[nt*4 + (lane & 3)];
                int colb = nt*8 + 2*(lane & 3);
                float sx = 0.f, sy = 0.f;
#pragma unroll
                for (int mt = 0; mt < 2; mt++)
#pragma unroll
                    for (int hf = 0; hf < 2; hf++) {
                        float2 fy = __ldg((const float2*)(rb + (size_t)si[mt][hf]*H + colb));
                        float cfv = cf[mt][hf];
                        sx += (acc[mt][nt][2*hf+0] + bb.x) * fy.x * cfv;
                        sy += (acc[mt][nt][2*hf+1] + bb.y) * fy.y * cfv;
                    }
                u64 v = pk2(sx, sy);
                v = f2add(v, __shfl_xor_sync(FULLMASK, v, 4));
                v = f2add(v, __shfl_xor_sync(FULLMASK, v, 8));
                v = f2add(v, __shfl_xor_sync(FULLMASK, v, 16));
                red[nt] = v;
            }
            u64 myd = red[0];
#pragma unroll
            for (int nt = 1; nt < 8; nt++)
                if ((lane >> 2) == nt) myd = red[nt];
            ((u64*)g_dec)[(size_t)q * 32 + lane] = myd;
        }
    }
}

// ======== zero-init for atomic projection output ========
__global__ void zero_out_kernel(float* __restrict__ out) {
    int i = blockIdx.x * 256 + threadIdx.x;
    if (i < NB * NQ * COUT) out[i] = 0.0f;
}

// ======== projection kernel: split hidden dim across 2 blocks/row-batch ========
static constexpr int PTHREADS = 128;
static constexpr int PGRID    = 2 * NB * NQ / PTHREADS;   // 512
static constexpr int POFF_WP0 = 0;          // 8192 floats: wp0 half [64][128]
static constexpr int POFF_BP0 = 8192;       // 128
static constexpr int POFF_WP1 = 8320;       // 384: wp1 half [128][3]
static constexpr int POFF_BP1 = 8704;       // 3 (+1)
static constexpr int PSMEM_FLOATS = 8708;
static constexpr int PSMEM_BYTES  = PSMEM_FLOATS * 4;   // 34832 B

__global__ void __launch_bounds__(PTHREADS)
proj_kernel(const float* __restrict__ wp0, const float* __restrict__ bp0,
            const float* __restrict__ wp1, const float* __restrict__ bp1,
            float* __restrict__ out)
{
    extern __shared__ float psm[];
    const int tid = threadIdx.x;
    const int hb  = blockIdx.x & 1;                 // hidden half
    const int row = (blockIdx.x >> 1) * PTHREADS + tid;

    for (int t = tid; t < H*128; t += PTHREADS) {
        int i = t >> 7, c = t & 127;
        psm[POFF_WP0 + t] = wp0[i*PH + hb*128 + c];
    }
    for (int t = tid; t < 128; t += PTHREADS) psm[POFF_BP0 + t] = bp0[hb*128 + t];
    for (int t = tid; t < 128*COUT; t += PTHREADS) psm[POFF_WP1 + t] = wp1[hb*128*COUT + t];
    if (tid < COUT) psm[POFF_BP1 + tid] = bp1[tid];
    __syncthreads();

    float dec[64];
    {
        const float4* dp = (const float4*)(g_dec + (size_t)row * H);
#pragma unroll
        for (int i = 0; i < 16; i++) {
            float4 v = dp[i];
            dec[4*i+0] = v.x; dec[4*i+1] = v.y;
            dec[4*i+2] = v.z; dec[4*i+3] = v.w;
        }
    }

    float o0 = hb ? 0.f : psm[POFF_BP1+0];
    float o1 = hb ? 0.f : psm[POFF_BP1+1];
    float o2 = hb ? 0.f : psm[POFF_BP1+2];

#pragma unroll 1
    for (int cc = 0; cc < 2; cc++) {              // 2 chunks of 64 local hidden
        u64 a[32];
        {
            const u64* bp = (const u64*)(psm + POFF_BP0 + cc * 64);
#pragma unroll
            for (int p = 0; p < 32; p++) a[p] = bp[p];
        }
#pragma unroll 4
        for (int i = 0; i < 64; i++) {
            u64 dd = pk2(dec[i], dec[i]);
            const ulonglong2* wr =
                (const ulonglong2*)(psm + POFF_WP0 + i*128 + cc*64);
#pragma unroll
            for (int j2 = 0; j2 < 16; j2++) {
                ulonglong2 w = wr[j2];            // warp-uniform LDS.128 broadcast
                a[2*j2]   = f2fma(dd, w.x, a[2*j2]);
                a[2*j2+1] = f2fma(dd, w.y, a[2*j2+1]);
            }
        }
#pragma unroll
        for (int p = 0; p < 32; p++) {
            float x, y; upk2(a[p], x, y);
            float g0 = gelu_f(x), g1 = gelu_f(y);
            int jj = cc * 64 + 2 * p;             // local hidden index
            o0 = fmaf(g0, psm[POFF_WP1 + jj*3 + 0], o0);
            o1 = fmaf(g0, psm[POFF_WP1 + jj*3 + 1], o1);
            o2 = fmaf(g0, psm[POFF_WP1 + jj*3 + 2], o2);
            o0 = fmaf(g1, psm[POFF_WP1 + jj*3 + 3], o0);
            o1 = fmaf(g1, psm[POFF_WP1 + jj*3 + 4], o1);
            o2 = fmaf(g1, psm[POFF_WP1 + jj*3 + 5], o2);
        }
    }

    atomicAdd(out + row*3 + 0, o0);
    atomicAdd(out + row*3 + 1, o1);
    atomicAdd(out + row*3 + 2, o2);
}

extern "C" void kernel_launch(void* const* d_in, const int* in_sizes, int n_in,
                              void* d_out, int out_size) {
    const float* lat  = (const float*)d_in[0];
    const float* rnd  = (const float*)d_in[1];
    const float* qry  = (const float*)d_in[2];
    const float* we0  = (const float*)d_in[3];
    const float* be0  = (const float*)d_in[4];
    const float* we1  = (const float*)d_in[5];
    const float* be1  = (const float*)d_in[6];
    const float* we2  = (const float*)d_in[7];
    const float* be2  = (const float*)d_in[8];
    const float* wsw0 = (const float*)d_in[9];
    const float* bsw0 = (const float*)d_in[10];
    const float* wsw1 = (const float*)d_in[11];
    const float* bsw1 = (const float*)d_in[12];
    const float* wp0  = (const float*)d_in[13];
    const float* bp0  = (const float*)d_in[14];
    const float* wp1  = (const float*)d_in[15];
    const float* bp1  = (const float*)d_in[16];
    float* out = (float*)d_out;

    cudaFuncSetAttribute(magno_kernel, cudaFuncAttributeMaxDynamicSharedMemorySize, SMEM_BYTES);
    cudaFuncSetAttribute(proj_kernel,  cudaFuncAttributeMaxDynamicSharedMemorySize, PSMEM_BYTES);
    zero_out_kernel<<<(NB*NQ*COUT + 255)/256, 256>>>(out);
    magno_kernel<<<NBLOCK, THREADS, SMEM_BYTES>>>(
        lat, rnd, qry, we0, be0, we1, be1, we2, be2,
        wsw0, bsw0, wsw1, bsw1);
    proj_kernel<<<PGRID, PTHREADS, PSMEM_BYTES>>>(wp0, bp0, wp1, bp1, out);
}

// round 15
// speedup vs baseline: 1.3729x; 1.1094x over previous
#include <cuda_runtime.h>
#include <cuda_bf16.h>
#include <math.h>
#include <cstdint>

#define FULLMASK 0xffffffffu
typedef unsigned long long u64;

static constexpr int NL     = 2048;
static constexpr int NQ     = 16384;
static constexpr int NB     = 2;
static constexpr int H      = 64;
static constexpr int PH     = 256;
static constexpr int COUT   = 3;
static constexpr int KCAP   = 32;
static constexpr int CAP    = 160;
static constexpr int THREADS= 128;
static constexpr int WARPS  = 4;
static constexpr int NBLOCK = 444;   // 148 SMs x 3 CTAs
static constexpr int GRIDW  = 9;     // 9x9 cells; 1/9 > 0.11 radius
static constexpr int NCELL  = GRIDW * GRIDW;

// device scratch
__device__ float  g_dec[NB * NQ * H];     // 8 MB
__device__ int    g_cell[NL];
__device__ int    g_cnt[NCELL];
__device__ int    g_cellstart[NCELL + 1];
__device__ float4 g_spack[NL];            // {x, y, bitcast(idx), 0}

// ---- main-kernel SMEM byte offsets ----
static constexpr int OFF_ASTG  = 0;       // 4 warps x 4096 (A staging)         = 16384
static constexpr int OFF_FRAGB = 16384;   // 4 arrays x 1024 u64 (B fragments)  = 32768
static constexpr int OFF_CAND  = 49152;   // 4 warps x 160 u64                  = 5120
static constexpr int OFF_WE0   = 54272;   // 256 f32
static constexpr int OFF_BE0   = 55296;   // 64 f32
static constexpr int OFF_BE1   = 55552;
static constexpr int OFF_BE2   = 55808;
static constexpr int OFF_WSW0  = 56064;
static constexpr int OFF_BSW0  = 56192;
static constexpr int OFF_WSW1  = 56256;
static constexpr int OFF_BSW1  = 56384;   // 2 f32
static constexpr int OFF_CS    = 56448;   // 82 ints = 328 B
static constexpr int SMEM_BYTES= 56832;   // x3 CTAs = 166.5KB; L1D ~57KB

// ---------- helpers ----------
__device__ __forceinline__ uint32_t smem_to_u32(const void* p) {
    uint32_t a;
    asm("{ .reg .u64 t; cvta.to.shared.u64 t, %1; cvt.u32.u64 %0, t; }" : "=r"(a) : "l"(p));
    return a;
}
__device__ __forceinline__ uint32_t pkbf(float lo, float hi) {
    uint32_t r; asm("cvt.rn.bf16x2.f32 %0, %1, %2;" : "=r"(r) : "f"(hi), "f"(lo)); return r;
}
__device__ __forceinline__ float lof(float x) {
    return x - __bfloat162float(__float2bfloat16(x));
}
__device__ __forceinline__ void hmma(float c[4], const uint32_t a[4], uint32_t b0, uint32_t b1) {
    asm volatile("mma.sync.aligned.m16n8k16.row.col.f32.bf16.bf16.f32 "
        "{%0,%1,%2,%3}, {%4,%5,%6,%7}, {%8,%9}, {%0,%1,%2,%3};"
        : "+f"(c[0]), "+f"(c[1]), "+f"(c[2]), "+f"(c[3])
        : "r"(a[0]), "r"(a[1]), "r"(a[2]), "r"(a[3]), "r"(b0), "r"(b1));
}
__device__ __forceinline__ void ldsm4(uint32_t r[4], uint32_t addr) {
    asm volatile("ldmatrix.sync.aligned.m8n8.x4.shared.b16 {%0,%1,%2,%3}, [%4];"
        : "=r"(r[0]), "=r"(r[1]), "=r"(r[2]), "=r"(r[3]) : "r"(addr));
}
__device__ __forceinline__ u64 pk2(float a, float b) {
    u64 r; asm("mov.b64 %0,{%1,%2};" : "=l"(r) : "f"(a), "f"(b)); return r;
}
__device__ __forceinline__ void upk2(u64 v, float& a, float& b) {
    asm("mov.b64 {%0,%1},%2;" : "=f"(a), "=f"(b) : "l"(v));
}
__device__ __forceinline__ u64 f2fma(u64 a, u64 b, u64 c) {
    u64 d; asm("fma.rn.f32x2 %0,%1,%2,%3;" : "=l"(d) : "l"(a), "l"(b), "l"(c)); return d;
}
__device__ __forceinline__ u64 f2add(u64 a, u64 b) {
    u64 d; asm("add.rn.f32x2 %0,%1,%2;" : "=l"(d) : "l"(a), "l"(b)); return d;
}
__device__ __forceinline__ unsigned redux_min_u32(unsigned v) {
    unsigned r; asm("redux.sync.min.u32 %0, %1, 0xffffffff;" : "=r"(r) : "r"(v)); return r;
}
__device__ __forceinline__ float gelu_f(float x) {
    float z = fabsf(x) * 0.7071067811865476f;
    float t = __fdividef(1.0f, fmaf(0.3275911f, z, 1.0f));
    float p = t * fmaf(t, fmaf(t, fmaf(t, fmaf(t, 1.061405429f, -1.453152027f),
                                        1.421413741f), -0.284496736f), 0.254829592f);
    float e = __expf(-z * z);
    float er = fmaf(-p, e, 1.0f);
    er = copysignf(er, x);
    return 0.5f * x * (1.0f + er);
}
__device__ __forceinline__ void ce(u64& a, u64& b) {
    u64 lo = a < b ? a : b;
    u64 hi = a < b ? b : a;
    a = lo; b = hi;
}
__device__ __forceinline__ int cell_of(float x) {
    int c = (int)(x * (float)GRIDW);
    return c < 0 ? 0 : (c > GRIDW-1 ? GRIDW-1 : c);
}

// ======== setup kernels ========
__global__ void zero_out_kernel(float* __restrict__ out) {
    int i = blockIdx.x * 256 + threadIdx.x;
    if (i < NB * NQ * COUT) out[i] = 0.0f;
    if (i < NCELL) g_cnt[i] = 0;
}
__global__ void setupA_kernel(const float* __restrict__ lat) {
    int i = blockIdx.x * 256 + threadIdx.x;
    if (i < NL) {
        int cx = cell_of(lat[2*i]), cy = cell_of(lat[2*i+1]);
        int c = cy * GRIDW + cx;
        g_cell[i] = c;
        atomicAdd(&g_cnt[c], 1);
    }
}
__global__ void setupB_kernel() {
    if (threadIdx.x == 0) {
        int s = 0;
        for (int c = 0; c < NCELL; c++) { g_cellstart[c] = s; s += g_cnt[c]; }
        g_cellstart[NCELL] = s;
    }
}
__global__ void setupC_kernel(const float* __restrict__ lat) {
    const int c = blockIdx.x;           // one warp per cell
    const int lane = threadIdx.x;
    const unsigned lt_mask = (1u << lane) - 1u;
    int base = g_cellstart[c];
    int cur = 0;
    for (int i = lane; i < NL; i += 32) {
        bool m = (g_cell[i] == c);
        unsigned bm = __ballot_sync(FULLMASK, m);
        if (m) {
            int pos = base + cur + __popc(bm & lt_mask);
            g_spack[pos] = make_float4(lat[2*i], lat[2*i+1], __int_as_float(i), 0.0f);
        }
        cur += __popc(bm);
    }
}

__global__ void __launch_bounds__(THREADS, 3)
magno_kernel(const float* __restrict__ lat,  const float* __restrict__ rnd,
             const float* __restrict__ qry,
             const float* __restrict__ we0,  const float* __restrict__ be0,
             const float* __restrict__ we1,  const float* __restrict__ be1,
             const float* __restrict__ we2,  const float* __restrict__ be2,
             const float* __restrict__ wsw0, const float* __restrict__ bsw0,
             const float* __restrict__ wsw1, const float* __restrict__ bsw1)
{
    extern __shared__ char smem[];
    const uint32_t smem_base = smem_to_u32(smem);
    const int tid = threadIdx.x, warp = tid >> 5, lane = tid & 31;

    // ---- B fragments: arrays 0=W1hi 1=W1lo 2=W2hi 3=W2lo ----
    {
        u64* fbw = (u64*)(smem + OFF_FRAGB);
        for (int i = tid; i < 4096; i += THREADS) {
            int arr = i >> 10, rem = i & 1023;
            int frag = rem >> 5, l = rem & 31;
            int kt = frag >> 3, nt = frag & 7;
            int k0 = kt*16 + 2*(l & 3);
            int n  = nt*8 + (l >> 2);
            const float* W = (arr < 2) ? we1 : we2;
            float w00 = W[(k0  )*H + n], w01 = W[(k0+1)*H + n];
            float w10 = W[(k0+8)*H + n], w11 = W[(k0+9)*H + n];
            if (arr & 1) { w00 = lof(w00); w01 = lof(w01); w10 = lof(w10); w11 = lof(w11); }
            fbw[i] = (u64)pkbf(w00, w01) | ((u64)pkbf(w10, w11) << 32);
        }
    }
    {
        float* f = (float*)smem;
        for (int t = tid; t < 4*H; t += THREADS) f[OFF_WE0/4 + t] = we0[t];
        for (int t = tid; t < H;   t += THREADS) {
            f[OFF_BE0/4 + t] = be0[t];
            f[OFF_BE1/4 + t] = be1[t];
            f[OFF_BE2/4 + t] = be2[t];
        }
        if (tid < 32)              f[OFF_WSW0/4 + tid]    = wsw0[tid];
        if (tid < 16)              f[OFF_BSW0/4 + tid]    = bsw0[tid];
        if (tid >= 32 && tid < 64) f[OFF_WSW1/4 + tid-32] = wsw1[tid-32];
        if (tid >= 64 && tid < 66) f[OFF_BSW1/4 + tid-64] = bsw1[tid-64];
        int* cs = (int*)(smem + OFF_CS);
        for (int t = tid; t < NCELL+1; t += THREADS) cs[t] = g_cellstart[t];
    }
    __syncthreads();

    u64* cand = (u64*)(smem + OFF_CAND) + warp * CAP;
    const u64* fb = (const u64*)(smem + OFF_FRAGB);
    const int* cs = (const int*)(smem + OFF_CS);
    const float2* latf2 = (const float2*)lat;
    const float* smf = (const float*)smem;
    char* astg = smem + OFF_ASTG + warp * 4096;
    const uint32_t astg_u32 = smem_base + OFF_ASTG + warp * 4096;

    const float R0SQ = (float)(0.055 * 0.055);
    const float R1SQ = (float)(0.11  * 0.11);
    const unsigned lt_mask = (1u << lane) - 1u;

    for (int q = blockIdx.x * WARPS + warp; q < NB * NQ; q += gridDim.x * WARPS) {
        const int  bix = q >> 14;
        const float qx = qry[2*q], qy = qry[2*q+1];

        // ---- scale-mixing weights ----
        float s0 = smf[OFF_BSW1/4+0], s1 = smf[OFF_BSW1/4+1];
#pragma unroll
        for (int t = 0; t < 16; t++) {
            float z = smf[OFF_BSW0/4+t] + qx*smf[OFF_WSW0/4+t] + qy*smf[OFF_WSW0/4+16+t];
            z = fmaxf(z, 0.0f);
            s0 = fmaf(z, smf[OFF_WSW1/4+2*t+0], s0);
            s1 = fmaf(z, smf[OFF_WSW1/4+2*t+1], s1);
        }
        float mx = fmaxf(s0, s1);
        float e0 = __expf(s0 - mx), e1 = __expf(s1 - mx);
        float inv = __fdividef(1.0f, e0 + e1);
        float sw0v = e0 * inv, sw1v = e1 * inv;

        // ---- candidate collection via 9x9 grid (3 contiguous CSR ranges) ----
        int cnt = 0;
        {
            const int qcx = cell_of(qx), qcy = cell_of(qy);
            const int rx0 = qcx > 0 ? qcx-1 : 0;
            const int rx1 = qcx < GRIDW-1 ? qcx+1 : GRIDW-1;
            const int ry0 = qcy > 0 ? qcy-1 : 0;
            const int ry1 = qcy < GRIDW-1 ? qcy+1 : GRIDW-1;
#pragma unroll 1
            for (int ry = ry0; ry <= ry1; ry++) {
                int beg = cs[ry*GRIDW + rx0];
                int end = cs[ry*GRIDW + rx1 + 1];
#pragma unroll 1
                for (int t0 = beg; t0 < end; t0 += 32) {
                    int p = t0 + lane;
                    bool pr = false;
                    float d2 = 0.0f;
                    unsigned idx = 0;
                    if (p < end) {
                        float4 sp = __ldg(g_spack + p);
                        float dx = qx - sp.x, dy = qy - sp.y;
                        d2 = __fadd_rn(__fmul_rn(dx, dx), __fmul_rn(dy, dy));
                        idx = (unsigned)__float_as_int(sp.z);
                        pr = d2 <= R1SQ;
                    }
                    unsigned m = __ballot_sync(FULLMASK, pr);
                    if (pr) {
                        int pos = cnt + __popc(m & lt_mask);
                        if (pos < CAP)
                            cand[pos] = ((u64)__float_as_uint(d2) << 32) | idx;
                    }
                    cnt += __popc(m);
                }
            }
        }
        if (cnt > CAP) cnt = CAP;
        __syncwarp();

        // ---- exact K=32 selection ----
        u64 mykey = 0x7f7fffff00000000ull;
        int nsel;
        if (cnt <= KCAP) {
            nsel = cnt;
            if (lane < cnt) mykey = cand[lane];
        } else {
            nsel = KCAP;
            u64 c0, c1, c2, c3, c4, c5;
            c0 = (lane       < cnt) ? cand[lane      ] : ~0ull;
            c1 = (lane + 32  < cnt) ? cand[lane + 32 ] : ~0ull;
            c2 = (lane + 64  < cnt) ? cand[lane + 64 ] : ~0ull;
            c3 = (lane + 96  < cnt) ? cand[lane + 96 ] : ~0ull;
            c4 = (lane + 128 < cnt) ? cand[lane + 128] : ~0ull;
            c5 = ~0ull;
            ce(c0,c1); ce(c2,c3); ce(c4,c5);
            ce(c0,c2); ce(c3,c5); ce(c1,c4);
            ce(c0,c1); ce(c2,c3); ce(c4,c5);
            ce(c1,c2); ce(c3,c4); ce(c2,c3);
            unsigned hdb = (unsigned)(c0 >> 32);
#pragma unroll 1
            for (int r = 0; r < KCAP; r++) {
                unsigned m = redux_min_u32(hdb);
                unsigned tied = __ballot_sync(FULLMASK, hdb == m);
                int src;
                if ((tied & (tied - 1u)) == 0u) {
                    src = __ffs(tied) - 1;
                } else {
                    unsigned lw = (hdb == m) ? (unsigned)c0 : 0xffffffffu;
                    unsigned mi = redux_min_u32(lw);
                    src = __ffs(__ballot_sync(FULLMASK, lw == mi)) - 1;
                }
                u64 win = __shfl_sync(FULLMASK, c0, src);
                if (lane == r) mykey = win;
                bool pop = (lane == src);
                c0 = pop ? c1 : c0; c1 = pop ? c2 : c1; c2 = pop ? c3 : c2;
                c3 = pop ? c4 : c3; c4 = pop ? c5 : c4; c5 = pop ? ~0ull : c5;
                hdb = (unsigned)(c0 >> 32);
            }
        }
        float seld2  = __uint_as_float((unsigned)(mykey >> 32));
        int   selidx = (int)(mykey & 0xffffffffu);
        if (lane >= nsel) { seld2 = 3.4e38f; selidx = 0; }

        bool v0 = (lane < nsel) && (seld2 <= R0SQ);
        int  c0cnt = __popc(__ballot_sync(FULLMASK, v0));
        float coeff = 0.0f;
        if (v0)          coeff += sw0v / (float)(c0cnt > 1 ? c0cnt : 1);
        if (lane < nsel) coeff += sw1v / (float)(nsel  > 1 ? nsel  : 1);

        {
            const float* frowf = rnd + (size_t)(bix * NL + selidx) * H;
            asm volatile("prefetch.global.L1 [%0];" :: "l"(frowf));
            asm volatile("prefetch.global.L1 [%0];" :: "l"(frowf + 32));
        }

        // ---- layer 0 (lane = neighbor row), pack bf16 hi/lo ----
        uint32_t hiP[32], loP[32];
        {
            float2 yc = __ldg(latf2 + selidx);
            u64 yx2 = pk2(yc.x, yc.x), yy2 = pk2(yc.y, yc.y);
            u64 qx2 = pk2(qx, qx),     qy2 = pk2(qy, qy);
            const u64* w0r0 = (const u64*)(smem + OFF_WE0);
            const u64* w0r1 = (const u64*)(smem + OFF_WE0 + 256);
            const u64* w0r2 = (const u64*)(smem + OFF_WE0 + 512);
            const u64* w0r3 = (const u64*)(smem + OFF_WE0 + 768);
            const u64* b0p  = (const u64*)(smem + OFF_BE0);
#pragma unroll
            for (int jp = 0; jp < 32; jp++) {
                u64 t = b0p[jp];
                t = f2fma(yx2, w0r0[jp], t);
                t = f2fma(yy2, w0r1[jp], t);
                t = f2fma(qx2, w0r2[jp], t);
                t = f2fma(qy2, w0r3[jp], t);
                float a, b; upk2(t, a, b);
                float g0 = gelu_f(a), g1 = gelu_f(b);
                hiP[jp] = pkbf(g0, g1);
                loP[jp] = pkbf(lof(g0), lof(g1));
            }
        }

        // ---- stage hi/lo, ldmatrix A fragments ----
        uint32_t Ahi[2][4][4], Alo[2][4][4];
        __syncwarp();
#pragma unroll
        for (int c = 0; c < 8; c++) {
            uint32_t off = (uint32_t)(lane*128 + ((c ^ (lane & 7)) << 4));
            *(uint4*)(astg + off) = make_uint4(hiP[4*c], hiP[4*c+1], hiP[4*c+2], hiP[4*c+3]);
        }
        __syncwarp();
#pragma unroll
        for (int mt = 0; mt < 2; mt++)
#pragma unroll
            for (int kt = 0; kt < 4; kt++) {
                int row = mt*16 + (lane & 15);
                int chunk = 2*kt + (lane >> 4);
                ldsm4(Ahi[mt][kt], astg_u32 + row*128 + ((chunk ^ (row & 7)) << 4));
            }
        __syncwarp();
#pragma unroll
        for (int c = 0; c < 8; c++) {
            uint32_t off = (uint32_t)(lane*128 + ((c ^ (lane & 7)) << 4));
            *(uint4*)(astg + off) = make_uint4(loP[4*c], loP[4*c+1], loP[4*c+2], loP[4*c+3]);
        }
        __syncwarp();
#pragma unroll
        for (int mt = 0; mt < 2; mt++)
#pragma unroll
            for (int kt = 0; kt < 4; kt++) {
                int row = mt*16 + (lane & 15);
                int chunk = 2*kt + (lane >> 4);
                ldsm4(Alo[mt][kt], astg_u32 + row*128 + ((chunk ^ (row & 7)) << 4));
            }

        // ---- layer 1 ----
        float acc[2][8][4];
#pragma unroll
        for (int mt = 0; mt < 2; mt++)
#pragma unroll
            for (int nt = 0; nt < 8; nt++)
#pragma unroll
                for (int r = 0; r < 4; r++) acc[mt][nt][r] = 0.0f;

#define PASS(AREG, ARR) \
        _Pragma("unroll") \
        for (int kt = 0; kt < 4; kt++) { \
            u64 bf[8]; \
            _Pragma("unroll") \
            for (int nt = 0; nt < 8; nt++) bf[nt] = fb[(ARR)*1024 + (kt*8+nt)*32 + lane]; \
            _Pragma("unroll") \
            for (int mt = 0; mt < 2; mt++) \
            _Pragma("unroll") \
            for (int nt = 0; nt < 8; nt++) \
                hmma(acc[mt][nt], AREG[mt][kt], (uint32_t)bf[nt], (uint32_t)(bf[nt] >> 32)); \
        }

        PASS(Ahi, 0)
        PASS(Alo, 0)
        PASS(Ahi, 1)

        // ---- bias + gelu + re-fragment ----
        uint32_t A2hi[2][4][4], A2lo[2][4][4];
        {
            const float2* b1p = (const float2*)(smem + OFF_BE1);
#pragma unroll
            for (int mt = 0; mt < 2; mt++)
#pragma unroll
                for (int j = 0; j < 4; j++)
#pragma unroll
                    for (int s = 0; s < 2; s++) {
                        int nt = 2*j + s;
                        float2 bb = b1p[nt*4 + (lane & 3)];
                        float g0 = gelu_f(acc[mt][nt][0] + bb.x);
                        float g1 = gelu_f(acc[mt][nt][1] + bb.y);
                        float g2 = gelu_f(acc[mt][nt][2] + bb.x);
                        float g3 = gelu_f(acc[mt][nt][3] + bb.y);
                        A2hi[mt][j][2*s]   = pkbf(g0, g1);
                        A2hi[mt][j][2*s+1] = pkbf(g2, g3);
                        A2lo[mt][j][2*s]   = pkbf(lof(g0), lof(g1));
                        A2lo[mt][j][2*s+1] = pkbf(lof(g2), lof(g3));
                    }
        }

        // ---- layer 2 ----
#pragma unroll
        for (int mt = 0; mt < 2; mt++)
#pragma unroll
            for (int nt = 0; nt < 8; nt++)
#pragma unroll
                for (int r = 0; r < 4; r++) acc[mt][nt][r] = 0.0f;

        PASS(A2hi, 2)
        PASS(A2lo, 2)
        PASS(A2hi, 3)
#undef PASS

        // ---- epilogue in fragment layout ----
        {
            float cf[2][2]; int si[2][2];
#pragma unroll
            for (int mt = 0; mt < 2; mt++)
#pragma unroll
                for (int hf = 0; hf < 2; hf++) {
                    int src = mt*16 + (lane >> 2) + 8*hf;
                    cf[mt][hf] = __shfl_sync(FULLMASK, coeff,  src);
                    si[mt][hf] = __shfl_sync(FULLMASK, selidx, src);
                }
            const float* rb = rnd + (size_t)bix * NL * H;
            const float2* b2p = (const float2*)(smem + OFF_BE2);
            u64 red[8];
#pragma unroll
            for (int nt = 0; nt < 8; nt++) {
                float2 bb = b2p[nt*4 + (lane & 3)];
                int colb = nt*8 + 2*(lane & 3);
                float sx = 0.f, sy = 0.f;
#pragma unroll
                for (int mt = 0; mt < 2; mt++)
#pragma unroll
                    for (int hf = 0; hf < 2; hf++) {
                        float2 fy = __ldg((const float2*)(rb + (size_t)si[mt][hf]*H + colb));
                        float cfv = cf[mt][hf];
                        sx += (acc[mt][nt][2*hf+0] + bb.x) * fy.x * cfv;
                        sy += (acc[mt][nt][2*hf+1] + bb.y) * fy.y * cfv;
                    }
                u64 v = pk2(sx, sy);
                v = f2add(v, __shfl_xor_sync(FULLMASK, v, 4));
                v = f2add(v, __shfl_xor_sync(FULLMASK, v, 8));
                v = f2add(v, __shfl_xor_sync(FULLMASK, v, 16));
                red[nt] = v;
            }
            u64 myd = red[0];
#pragma unroll
            for (int nt = 1; nt < 8; nt++)
                if ((lane >> 2) == nt) myd = red[nt];
            ((u64*)g_dec)[(size_t)q * 32 + lane] = myd;
        }
    }
}

// ======== projection kernel: split hidden dim across 2 blocks/row-batch ========
static constexpr int PTHREADS = 128;
static constexpr int PGRID    = 2 * NB * NQ / PTHREADS;   // 512
static constexpr int POFF_WP0 = 0;
static constexpr int POFF_BP0 = 8192;
static constexpr int POFF_WP1 = 8320;
static constexpr int POFF_BP1 = 8704;
static constexpr int PSMEM_FLOATS = 8708;
static constexpr int PSMEM_BYTES  = PSMEM_FLOATS * 4;

__global__ void __launch_bounds__(PTHREADS)
proj_kernel(const float* __restrict__ wp0, const float* __restrict__ bp0,
            const float* __restrict__ wp1, const float* __restrict__ bp1,
            float* __restrict__ out)
{
    extern __shared__ float psm[];
    const int tid = threadIdx.x;
    const int hb  = blockIdx.x & 1;
    const int row = (blockIdx.x >> 1) * PTHREADS + tid;

    for (int t = tid; t < H*128; t += PTHREADS) {
        int i = t >> 7, c = t & 127;
        psm[POFF_WP0 + t] = wp0[i*PH + hb*128 + c];
    }
    for (int t = tid; t < 128; t += PTHREADS) psm[POFF_BP0 + t] = bp0[hb*128 + t];
    for (int t = tid; t < 128*COUT; t += PTHREADS) psm[POFF_WP1 + t] = wp1[hb*128*COUT + t];
    if (tid < COUT) psm[POFF_BP1 + tid] = bp1[tid];
    __syncthreads();

    float dec[64];
    {
        const float4* dp = (const float4*)(g_dec + (size_t)row * H);
#pragma unroll
        for (int i = 0; i < 16; i++) {
            float4 v = dp[i];
            dec[4*i+0] = v.x; dec[4*i+1] = v.y;
            dec[4*i+2] = v.z; dec[4*i+3] = v.w;
        }
    }

    float o0 = hb ? 0.f : psm[POFF_BP1+0];
    float o1 = hb ? 0.f : psm[POFF_BP1+1];
    float o2 = hb ? 0.f : psm[POFF_BP1+2];

#pragma unroll 1
    for (int cc = 0; cc < 2; cc++) {
        u64 a[32];
        {
            const u64* bp = (const u64*)(psm + POFF_BP0 + cc * 64);
#pragma unroll
            for (int p = 0; p < 32; p++) a[p] = bp[p];
        }
#pragma unroll 4
        for (int i = 0; i < 64; i++) {
            u64 dd = pk2(dec[i], dec[i]);
            const ulonglong2* wr =
                (const ulonglong2*)(psm + POFF_WP0 + i*128 + cc*64);
#pragma unroll
            for (int j2 = 0; j2 < 16; j2++) {
                ulonglong2 w = wr[j2];
                a[2*j2]   = f2fma(dd, w.x, a[2*j2]);
                a[2*j2+1] = f2fma(dd, w.y, a[2*j2+1]);
            }
        }
#pragma unroll
        for (int p = 0; p < 32; p++) {
            float x, y; upk2(a[p], x, y);
            float g0 = gelu_f(x), g1 = gelu_f(y);
            int jj = cc * 64 + 2 * p;
            o0 = fmaf(g0, psm[POFF_WP1 + jj*3 + 0], o0);
            o1 = fmaf(g0, psm[POFF_WP1 + jj*3 + 1], o1);
            o2 = fmaf(g0, psm[POFF_WP1 + jj*3 + 2], o2);
            o0 = fmaf(g1, psm[POFF_WP1 + jj*3 + 3], o0);
            o1 = fmaf(g1, psm[POFF_WP1 + jj*3 + 4], o1);
            o2 = fmaf(g1, psm[POFF_WP1 + jj*3 + 5], o2);
        }
    }

    atomicAdd(out + row*3 + 0, o0);
    atomicAdd(out + row*3 + 1, o1);
    atomicAdd(out + row*3 + 2, o2);
}

extern "C" void kernel_launch(void* const* d_in, const int* in_sizes, int n_in,
                              void* d_out, int out_size) {
    const float* lat  = (const float*)d_in[0];
    const float* rnd  = (const float*)d_in[1];
    const float* qry  = (const float*)d_in[2];
    const float* we0  = (const float*)d_in[3];
    const float* be0  = (const float*)d_in[4];
    const float* we1  = (const float*)d_in[5];
    const float* be1  = (const float*)d_in[6];
    const float* we2  = (const float*)d_in[7];
    const float* be2  = (const float*)d_in[8];
    const float* wsw0 = (const float*)d_in[9];
    const float* bsw0 = (const float*)d_in[10];
    const float* wsw1 = (const float*)d_in[11];
    const float* bsw1 = (const float*)d_in[12];
    const float* wp0  = (const float*)d_in[13];
    const float* bp0  = (const float*)d_in[14];
    const float* wp1  = (const float*)d_in[15];
    const float* bp1  = (const float*)d_in[16];
    float* out = (float*)d_out;

    cudaFuncSetAttribute(magno_kernel, cudaFuncAttributeMaxDynamicSharedMemorySize, SMEM_BYTES);
    cudaFuncSetAttribute(proj_kernel,  cudaFuncAttributeMaxDynamicSharedMemorySize, PSMEM_BYTES);
    zero_out_kernel<<<(NB*NQ*COUT + 255)/256, 256>>>(out);
    setupA_kernel<<<(NL + 255)/256, 256>>>(lat);
    setupB_kernel<<<1, 32>>>();
    setupC_kernel<<<NCELL, 32>>>(lat);
    magno_kernel<<<NBLOCK, THREADS, SMEM_BYTES>>>(
        lat, rnd, qry, we0, be0, we1, be1, we2, be2,
        wsw0, bsw0, wsw1, bsw1);
    proj_kernel<<<PGRID, PTHREADS, PSMEM_BYTES>>>(wp0, bp0, wp1, bp1, out);
}

// round 16
// speedup vs baseline: 1.4427x; 1.0508x over previous
#include <cuda_runtime.h>
#include <cuda_bf16.h>
#include <math.h>
#include <cstdint>

#define FULLMASK 0xffffffffu
typedef unsigned long long u64;

static constexpr int NL     = 2048;
static constexpr int NQ     = 16384;
static constexpr int NB     = 2;
static constexpr int H      = 64;
static constexpr int PH     = 256;
static constexpr int COUT   = 3;
static constexpr int KCAP   = 32;
static constexpr int CAP    = 160;
static constexpr int THREADS= 128;
static constexpr int WARPS  = 4;
static constexpr int NBLOCK = 444;   // 148 SMs x 3 CTAs
static constexpr int GRIDW  = 9;     // 9x9 cells; 1/9 > 0.11 radius
static constexpr int NCELL  = GRIDW * GRIDW;

// device scratch
__device__ float  g_dec[NB * NQ * H];     // 8 MB
__device__ int    g_cellstart[NCELL + 1];
__device__ float4 g_spack[NL];            // {x, y, bitcast(idx), 0}

// ---- main-kernel SMEM byte offsets ----
static constexpr int OFF_ASTG  = 0;       // 4 warps x 4096 (A staging)         = 16384
static constexpr int OFF_FRAGB = 16384;   // 4 arrays x 1024 u64 (B fragments)  = 32768
static constexpr int OFF_CAND  = 49152;   // 4 warps x 160 u64                  = 5120
static constexpr int OFF_WE0   = 54272;   // 256 f32
static constexpr int OFF_BE0   = 55296;   // 64 f32
static constexpr int OFF_BE1   = 55552;
static constexpr int OFF_BE2   = 55808;
static constexpr int OFF_WSW0  = 56064;
static constexpr int OFF_BSW0  = 56192;
static constexpr int OFF_WSW1  = 56256;
static constexpr int OFF_BSW1  = 56384;   // 2 f32
static constexpr int OFF_CS    = 56448;   // 82 ints = 328 B
static constexpr int SMEM_BYTES= 56832;   // x3 CTAs = 166.5KB; L1D ~57KB

// ---------- helpers ----------
__device__ __forceinline__ uint32_t smem_to_u32(const void* p) {
    uint32_t a;
    asm("{ .reg .u64 t; cvta.to.shared.u64 t, %1; cvt.u32.u64 %0, t; }" : "=r"(a) : "l"(p));
    return a;
}
__device__ __forceinline__ uint32_t pkbf(float lo, float hi) {
    uint32_t r; asm("cvt.rn.bf16x2.f32 %0, %1, %2;" : "=r"(r) : "f"(hi), "f"(lo)); return r;
}
__device__ __forceinline__ float lof(float x) {
    return x - __bfloat162float(__float2bfloat16(x));
}
__device__ __forceinline__ void hmma(float c[4], const uint32_t a[4], uint32_t b0, uint32_t b1) {
    asm volatile("mma.sync.aligned.m16n8k16.row.col.f32.bf16.bf16.f32 "
        "{%0,%1,%2,%3}, {%4,%5,%6,%7}, {%8,%9}, {%0,%1,%2,%3};"
        : "+f"(c[0]), "+f"(c[1]), "+f"(c[2]), "+f"(c[3])
        : "r"(a[0]), "r"(a[1]), "r"(a[2]), "r"(a[3]), "r"(b0), "r"(b1));
}
__device__ __forceinline__ void ldsm4(uint32_t r[4], uint32_t addr) {
    asm volatile("ldmatrix.sync.aligned.m8n8.x4.shared.b16 {%0,%1,%2,%3}, [%4];"
        : "=r"(r[0]), "=r"(r[1]), "=r"(r[2]), "=r"(r[3]) : "r"(addr));
}
__device__ __forceinline__ u64 pk2(float a, float b) {
    u64 r; asm("mov.b64 %0,{%1,%2};" : "=l"(r) : "f"(a), "f"(b)); return r;
}
__device__ __forceinline__ void upk2(u64 v, float& a, float& b) {
    asm("mov.b64 {%0,%1},%2;" : "=f"(a), "=f"(b) : "l"(v));
}
__device__ __forceinline__ u64 f2fma(u64 a, u64 b, u64 c) {
    u64 d; asm("fma.rn.f32x2 %0,%1,%2,%3;" : "=l"(d) : "l"(a), "l"(b), "l"(c)); return d;
}
__device__ __forceinline__ u64 f2add(u64 a, u64 b) {
    u64 d; asm("add.rn.f32x2 %0,%1,%2;" : "=l"(d) : "l"(a), "l"(b)); return d;
}
__device__ __forceinline__ unsigned redux_min_u32(unsigned v) {
    unsigned r; asm("redux.sync.min.u32 %0, %1, 0xffffffff;" : "=r"(r) : "r"(v)); return r;
}
__device__ __forceinline__ float gelu_f(float x) {
    float z = fabsf(x) * 0.7071067811865476f;
    float t = __fdividef(1.0f, fmaf(0.3275911f, z, 1.0f));
    float p = t * fmaf(t, fmaf(t, fmaf(t, fmaf(t, 1.061405429f, -1.453152027f),
                                        1.421413741f), -0.284496736f), 0.254829592f);
    float e = __expf(-z * z);
    float er = fmaf(-p, e, 1.0f);
    er = copysignf(er, x);
    return 0.5f * x * (1.0f + er);
}
__device__ __forceinline__ void ce(u64& a, u64& b) {
    u64 lo = a < b ? a : b;
    u64 hi = a < b ? b : a;
    a = lo; b = hi;
}
__device__ __forceinline__ int cell_of(float x) {
    int c = (int)(x * (float)GRIDW);
    return c < 0 ? 0 : (c > GRIDW-1 ? GRIDW-1 : c);
}

// ======== setup kernels ========
__global__ void zero_out_kernel(float* __restrict__ out) {
    int i = blockIdx.x * 256 + threadIdx.x;
    if (i < NB * NQ * COUT) out[i] = 0.0f;
}

// single-block fused bin + prefix + scatter (order within a cell is atomic-
// nondeterministic, but the downstream exact top-K selection is enumeration-
// order-invariant, so kernel OUTPUT is deterministic)
__global__ void __launch_bounds__(1024)
setup_kernel(const float* __restrict__ lat) {
    __shared__ int scnt[NCELL];
    __shared__ int soff[NCELL];
    __shared__ int sstart[NCELL + 1];
    const int tid = threadIdx.x;
    if (tid < NCELL) scnt[tid] = 0;
    __syncthreads();

    // bin 2 latents per thread
    float x0 = lat[2*tid],        y0 = lat[2*tid+1];
    float x1 = lat[2*(tid+1024)], y1 = lat[2*(tid+1024)+1];
    int c0 = cell_of(y0) * GRIDW + cell_of(x0);
    int c1 = cell_of(y1) * GRIDW + cell_of(x1);
    atomicAdd(&scnt[c0], 1);
    atomicAdd(&scnt[c1], 1);
    __syncthreads();

    if (tid == 0) {
        int s = 0;
#pragma unroll 1
        for (int c = 0; c < NCELL; c++) {
            sstart[c] = s;
            soff[c]   = s;
            s += scnt[c];
        }
        sstart[NCELL] = s;
    }
    __syncthreads();

    if (tid < NCELL + 1) g_cellstart[tid] = sstart[tid];

    int p0 = atomicAdd(&soff[c0], 1);
    g_spack[p0] = make_float4(x0, y0, __int_as_float(tid), 0.0f);
    int p1 = atomicAdd(&soff[c1], 1);
    g_spack[p1] = make_float4(x1, y1, __int_as_float(tid + 1024), 0.0f);
}

__global__ void __launch_bounds__(THREADS, 3)
magno_kernel(const float* __restrict__ lat,  const float* __restrict__ rnd,
             const float* __restrict__ qry,
             const float* __restrict__ we0,  const float* __restrict__ be0,
             const float* __restrict__ we1,  const float* __restrict__ be1,
             const float* __restrict__ we2,  const float* __restrict__ be2,
             const float* __restrict__ wsw0, const float* __restrict__ bsw0,
             const float* __restrict__ wsw1, const float* __restrict__ bsw1)
{
    extern __shared__ char smem[];
    const uint32_t smem_base = smem_to_u32(smem);
    const int tid = threadIdx.x, warp = tid >> 5, lane = tid & 31;

    // ---- B fragments: arrays 0=W1hi 1=W1lo 2=W2hi 3=W2lo ----
    {
        u64* fbw = (u64*)(smem + OFF_FRAGB);
        for (int i = tid; i < 4096; i += THREADS) {
            int arr = i >> 10, rem = i & 1023;
            int frag = rem >> 5, l = rem & 31;
            int kt = frag >> 3, nt = frag & 7;
            int k0 = kt*16 + 2*(l & 3);
            int n  = nt*8 + (l >> 2);
            const float* W = (arr < 2) ? we1 : we2;
            float w00 = W[(k0  )*H + n], w01 = W[(k0+1)*H + n];
            float w10 = W[(k0+8)*H + n], w11 = W[(k0+9)*H + n];
            if (arr & 1) { w00 = lof(w00); w01 = lof(w01); w10 = lof(w10); w11 = lof(w11); }
            fbw[i] = (u64)pkbf(w00, w01) | ((u64)pkbf(w10, w11) << 32);
        }
    }
    {
        float* f = (float*)smem;
        for (int t = tid; t < 4*H; t += THREADS) f[OFF_WE0/4 + t] = we0[t];
        for (int t = tid; t < H;   t += THREADS) {
            f[OFF_BE0/4 + t] = be0[t];
            f[OFF_BE1/4 + t] = be1[t];
            f[OFF_BE2/4 + t] = be2[t];
        }
        if (tid < 32)              f[OFF_WSW0/4 + tid]    = wsw0[tid];
        if (tid < 16)              f[OFF_BSW0/4 + tid]    = bsw0[tid];
        if (tid >= 32 && tid < 64) f[OFF_WSW1/4 + tid-32] = wsw1[tid-32];
        if (tid >= 64 && tid < 66) f[OFF_BSW1/4 + tid-64] = bsw1[tid-64];
        int* cs = (int*)(smem + OFF_CS);
        for (int t = tid; t < NCELL+1; t += THREADS) cs[t] = g_cellstart[t];
    }
    __syncthreads();

    u64* cand = (u64*)(smem + OFF_CAND) + warp * CAP;
    const u64* fb = (const u64*)(smem + OFF_FRAGB);
    const int* cs = (const int*)(smem + OFF_CS);
    const float2* latf2 = (const float2*)lat;
    const float* smf = (const float*)smem;
    char* astg = smem + OFF_ASTG + warp * 4096;
    const uint32_t astg_u32 = smem_base + OFF_ASTG + warp * 4096;

    const float R0SQ = (float)(0.055 * 0.055);
    const float R1SQ = (float)(0.11  * 0.11);
    const unsigned lt_mask = (1u << lane) - 1u;

    for (int q = blockIdx.x * WARPS + warp; q < NB * NQ; q += gridDim.x * WARPS) {
        const int  bix = q >> 14;
        const float qx = qry[2*q], qy = qry[2*q+1];

        // ---- scale-mixing weights ----
        float s0 = smf[OFF_BSW1/4+0], s1 = smf[OFF_BSW1/4+1];
#pragma unroll
        for (int t = 0; t < 16; t++) {
            float z = smf[OFF_BSW0/4+t] + qx*smf[OFF_WSW0/4+t] + qy*smf[OFF_WSW0/4+16+t];
            z = fmaxf(z, 0.0f);
            s0 = fmaf(z, smf[OFF_WSW1/4+2*t+0], s0);
            s1 = fmaf(z, smf[OFF_WSW1/4+2*t+1], s1);
        }
        float mx = fmaxf(s0, s1);
        float e0 = __expf(s0 - mx), e1 = __expf(s1 - mx);
        float inv = __fdividef(1.0f, e0 + e1);
        float sw0v = e0 * inv, sw1v = e1 * inv;

        // ---- candidate collection via 9x9 grid (3 contiguous CSR ranges) ----
        int cnt = 0;
        {
            const int qcx = cell_of(qx), qcy = cell_of(qy);
            const int rx0 = qcx > 0 ? qcx-1 : 0;
            const int rx1 = qcx < GRIDW-1 ? qcx+1 : GRIDW-1;
            const int ry0 = qcy > 0 ? qcy-1 : 0;
            const int ry1 = qcy < GRIDW-1 ? qcy+1 : GRIDW-1;
#pragma unroll 1
            for (int ry = ry0; ry <= ry1; ry++) {
                int beg = cs[ry*GRIDW + rx0];
                int end = cs[ry*GRIDW + rx1 + 1];
#pragma unroll 1
                for (int t0 = beg; t0 < end; t0 += 32) {
                    int p = t0 + lane;
                    bool pr = false;
                    float d2 = 0.0f;
                    unsigned idx = 0;
                    if (p < end) {
                        float4 sp = __ldg(g_spack + p);
                        float dx = qx - sp.x, dy = qy - sp.y;
                        d2 = __fadd_rn(__fmul_rn(dx, dx), __fmul_rn(dy, dy));
                        idx = (unsigned)__float_as_int(sp.z);
                        pr = d2 <= R1SQ;
                    }
                    unsigned m = __ballot_sync(FULLMASK, pr);
                    if (pr) {
                        int pos = cnt + __popc(m & lt_mask);
                        if (pos < CAP)
                            cand[pos] = ((u64)__float_as_uint(d2) << 32) | idx;
                    }
                    cnt += __popc(m);
                }
            }
        }
        if (cnt > CAP) cnt = CAP;
        __syncwarp();

        // ---- exact K=32 selection ----
        u64 mykey = 0x7f7fffff00000000ull;
        int nsel;
        if (cnt <= KCAP) {
            nsel = cnt;
            if (lane < cnt) mykey = cand[lane];
        } else {
            nsel = KCAP;
            u64 c0, c1, c2, c3, c4, c5;
            c0 = (lane       < cnt) ? cand[lane      ] : ~0ull;
            c1 = (lane + 32  < cnt) ? cand[lane + 32 ] : ~0ull;
            c2 = (lane + 64  < cnt) ? cand[lane + 64 ] : ~0ull;
            c3 = (lane + 96  < cnt) ? cand[lane + 96 ] : ~0ull;
            c4 = (lane + 128 < cnt) ? cand[lane + 128] : ~0ull;
            c5 = ~0ull;
            ce(c0,c1); ce(c2,c3); ce(c4,c5);
            ce(c0,c2); ce(c3,c5); ce(c1,c4);
            ce(c0,c1); ce(c2,c3); ce(c4,c5);
            ce(c1,c2); ce(c3,c4); ce(c2,c3);
            unsigned hdb = (unsigned)(c0 >> 32);
#pragma unroll 1
            for (int r = 0; r < KCAP; r++) {
                unsigned m = redux_min_u32(hdb);
                unsigned tied = __ballot_sync(FULLMASK, hdb == m);
                int src;
                if ((tied & (tied - 1u)) == 0u) {
                    src = __ffs(tied) - 1;
                } else {
                    unsigned lw = (hdb == m) ? (unsigned)c0 : 0xffffffffu;
                    unsigned mi = redux_min_u32(lw);
                    src = __ffs(__ballot_sync(FULLMASK, lw == mi)) - 1;
                }
                u64 win = __shfl_sync(FULLMASK, c0, src);
                if (lane == r) mykey = win;
                bool pop = (lane == src);
                c0 = pop ? c1 : c0; c1 = pop ? c2 : c1; c2 = pop ? c3 : c2;
                c3 = pop ? c4 : c3; c4 = pop ? c5 : c4; c5 = pop ? ~0ull : c5;
                hdb = (unsigned)(c0 >> 32);
            }
        }
        float seld2  = __uint_as_float((unsigned)(mykey >> 32));
        int   selidx = (int)(mykey & 0xffffffffu);
        if (lane >= nsel) { seld2 = 3.4e38f; selidx = 0; }

        bool v0 = (lane < nsel) && (seld2 <= R0SQ);
        int  c0cnt = __popc(__ballot_sync(FULLMASK, v0));
        float coeff = 0.0f;
        if (v0)          coeff += sw0v / (float)(c0cnt > 1 ? c0cnt : 1);
        if (lane < nsel) coeff += sw1v / (float)(nsel  > 1 ? nsel  : 1);

        {
            const float* frowf = rnd + (size_t)(bix * NL + selidx) * H;
            asm volatile("prefetch.global.L1 [%0];" :: "l"(frowf));
            asm volatile("prefetch.global.L1 [%0];" :: "l"(frowf + 32));
        }

        // ---- layer 0 (lane = neighbor row), pack bf16 hi/lo ----
        uint32_t hiP[32], loP[32];
        {
            float2 yc = __ldg(latf2 + selidx);
            u64 yx2 = pk2(yc.x, yc.x), yy2 = pk2(yc.y, yc.y);
            u64 qx2 = pk2(qx, qx),     qy2 = pk2(qy, qy);
            const u64* w0r0 = (const u64*)(smem + OFF_WE0);
            const u64* w0r1 = (const u64*)(smem + OFF_WE0 + 256);
            const u64* w0r2 = (const u64*)(smem + OFF_WE0 + 512);
            const u64* w0r3 = (const u64*)(smem + OFF_WE0 + 768);
            const u64* b0p  = (const u64*)(smem + OFF_BE0);
#pragma unroll
            for (int jp = 0; jp < 32; jp++) {
                u64 t = b0p[jp];
                t = f2fma(yx2, w0r0[jp], t);
                t = f2fma(yy2, w0r1[jp], t);
                t = f2fma(qx2, w0r2[jp], t);
                t = f2fma(qy2, w0r3[jp], t);
                float a, b; upk2(t, a, b);
                float g0 = gelu_f(a), g1 = gelu_f(b);
                hiP[jp] = pkbf(g0, g1);
                loP[jp] = pkbf(lof(g0), lof(g1));
            }
        }

        // ---- stage hi/lo, ldmatrix A fragments ----
        uint32_t Ahi[2][4][4], Alo[2][4][4];
        __syncwarp();
#pragma unroll
        for (int c = 0; c < 8; c++) {
            uint32_t off = (uint32_t)(lane*128 + ((c ^ (lane & 7)) << 4));
            *(uint4*)(astg + off) = make_uint4(hiP[4*c], hiP[4*c+1], hiP[4*c+2], hiP[4*c+3]);
        }
        __syncwarp();
#pragma unroll
        for (int mt = 0; mt < 2; mt++)
#pragma unroll
            for (int kt = 0; kt < 4; kt++) {
                int row = mt*16 + (lane & 15);
                int chunk = 2*kt + (lane >> 4);
                ldsm4(Ahi[mt][kt], astg_u32 + row*128 + ((chunk ^ (row & 7)) << 4));
            }
        __syncwarp();
#pragma unroll
        for (int c = 0; c < 8; c++) {
            uint32_t off = (uint32_t)(lane*128 + ((c ^ (lane & 7)) << 4));
            *(uint4*)(astg + off) = make_uint4(loP[4*c], loP[4*c+1], loP[4*c+2], loP[4*c+3]);
        }
        __syncwarp();
#pragma unroll
        for (int mt = 0; mt < 2; mt++)
#pragma unroll
            for (int kt = 0; kt < 4; kt++) {
                int row = mt*16 + (lane & 15);
                int chunk = 2*kt + (lane >> 4);
                ldsm4(Alo[mt][kt], astg_u32 + row*128 + ((chunk ^ (row & 7)) << 4));
            }

        // ---- layer 1 ----
        float acc[2][8][4];
#pragma unroll
        for (int mt = 0; mt < 2; mt++)
#pragma unroll
            for (int nt = 0; nt < 8; nt++)
#pragma unroll
                for (int r = 0; r < 4; r++) acc[mt][nt][r] = 0.0f;

#define PASS(AREG, ARR) \
        _Pragma("unroll") \
        for (int kt = 0; kt < 4; kt++) { \
            u64 bf[8]; \
            _Pragma("unroll") \
            for (int nt = 0; nt < 8; nt++) bf[nt] = fb[(ARR)*1024 + (kt*8+nt)*32 + lane]; \
            _Pragma("unroll") \
            for (int mt = 0; mt < 2; mt++) \
            _Pragma("unroll") \
            for (int nt = 0; nt < 8; nt++) \
                hmma(acc[mt][nt], AREG[mt][kt], (uint32_t)bf[nt], (uint32_t)(bf[nt] >> 32)); \
        }

        PASS(Ahi, 0)
        PASS(Alo, 0)
        PASS(Ahi, 1)

        // ---- bias + gelu + re-fragment ----
        uint32_t A2hi[2][4][4], A2lo[2][4][4];
        {
            const float2* b1p = (const float2*)(smem + OFF_BE1);
#pragma unroll
            for (int mt = 0; mt < 2; mt++)
#pragma unroll
                for (int j = 0; j < 4; j++)
#pragma unroll
                    for (int s = 0; s < 2; s++) {
                        int nt = 2*j + s;
                        float2 bb = b1p[nt*4 + (lane & 3)];
                        float g0 = gelu_f(acc[mt][nt][0] + bb.x);
                        float g1 = gelu_f(acc[mt][nt][1] + bb.y);
                        float g2 = gelu_f(acc[mt][nt][2] + bb.x);
                        float g3 = gelu_f(acc[mt][nt][3] + bb.y);
                        A2hi[mt][j][2*s]   = pkbf(g0, g1);
                        A2hi[mt][j][2*s+1] = pkbf(g2, g3);
                        A2lo[mt][j][2*s]   = pkbf(lof(g0), lof(g1));
                        A2lo[mt][j][2*s+1] = pkbf(lof(g2), lof(g3));
                    }
        }

        // ---- layer 2 ----
#pragma unroll
        for (int mt = 0; mt < 2; mt++)
#pragma unroll
            for (int nt = 0; nt < 8; nt++)
#pragma unroll
                for (int r = 0; r < 4; r++) acc[mt][nt][r] = 0.0f;

        PASS(A2hi, 2)
        PASS(A2lo, 2)
        PASS(A2hi, 3)
#undef PASS

        // ---- epilogue in fragment layout ----
        {
            float cf[2][2]; int si[2][2];
#pragma unroll
            for (int mt = 0; mt < 2; mt++)
#pragma unroll
                for (int hf = 0; hf < 2; hf++) {
                    int src = mt*16 + (lane >> 2) + 8*hf;
                    cf[mt][hf] = __shfl_sync(FULLMASK, coeff,  src);
                    si[mt][hf] = __shfl_sync(FULLMASK, selidx, src);
                }
            const float* rb = rnd + (size_t)bix * NL * H;
            const float2* b2p = (const float2*)(smem + OFF_BE2);
            u64 red[8];
#pragma unroll
            for (int nt = 0; nt < 8; nt++) {
                float2 bb = b2p[nt*4 + (lane & 3)];
                int colb = nt*8 + 2*(lane & 3);
                float sx = 0.f, sy = 0.f;
#pragma unroll
                for (int mt = 0; mt < 2; mt++)
#pragma unroll
                    for (int hf = 0; hf < 2; hf++) {
                        float2 fy = __ldg((const float2*)(rb + (size_t)si[mt][hf]*H + colb));
                        float cfv = cf[mt][hf];
                        sx += (acc[mt][nt][2*hf+0] + bb.x) * fy.x * cfv;
                        sy += (acc[mt][nt][2*hf+1] + bb.y) * fy.y * cfv;
                    }
                u64 v = pk2(sx, sy);
                v = f2add(v, __shfl_xor_sync(FULLMASK, v, 4));
                v = f2add(v, __shfl_xor_sync(FULLMASK, v, 8));
                v = f2add(v, __shfl_xor_sync(FULLMASK, v, 16));
                red[nt] = v;
            }
            u64 myd = red[0];
#pragma unroll
            for (int nt = 1; nt < 8; nt++)
                if ((lane >> 2) == nt) myd = red[nt];
            ((u64*)g_dec)[(size_t)q * 32 + lane] = myd;
        }
    }
}

// ======== projection kernel: split hidden dim across 2 blocks/row-batch ========
static constexpr int PTHREADS = 128;
static constexpr int PGRID    = 2 * NB * NQ / PTHREADS;   // 512
static constexpr int POFF_WP0 = 0;
static constexpr int POFF_BP0 = 8192;
static constexpr int POFF_WP1 = 8320;
static constexpr int POFF_BP1 = 8704;
static constexpr int PSMEM_FLOATS = 8708;
static constexpr int PSMEM_BYTES  = PSMEM_FLOATS * 4;

__global__ void __launch_bounds__(PTHREADS)
proj_kernel(const float* __restrict__ wp0, const float* __restrict__ bp0,
            const float* __restrict__ wp1, const float* __restrict__ bp1,
            float* __restrict__ out)
{
    extern __shared__ float psm[];
    const int tid = threadIdx.x;
    const int hb  = blockIdx.x & 1;
    const int row = (blockIdx.x >> 1) * PTHREADS + tid;

    for (int t = tid; t < H*128; t += PTHREADS) {
        int i = t >> 7, c = t & 127;
        psm[POFF_WP0 + t] = wp0[i*PH + hb*128 + c];
    }
    for (int t = tid; t < 128; t += PTHREADS) psm[POFF_BP0 + t] = bp0[hb*128 + t];
    for (int t = tid; t < 128*COUT; t += PTHREADS) psm[POFF_WP1 + t] = wp1[hb*128*COUT + t];
    if (tid < COUT) psm[POFF_BP1 + tid] = bp1[tid];
    __syncthreads();

    float dec[64];
    {
        const float4* dp = (const float4*)(g_dec + (size_t)row * H);
#pragma unroll
        for (int i = 0; i < 16; i++) {
            float4 v = dp[i];
            dec[4*i+0] = v.x; dec[4*i+1] = v.y;
            dec[4*i+2] = v.z; dec[4*i+3] = v.w;
        }
    }

    float o0 = hb ? 0.f : psm[POFF_BP1+0];
    float o1 = hb ? 0.f : psm[POFF_BP1+1];
    float o2 = hb ? 0.f : psm[POFF_BP1+2];

#pragma unroll 1
    for (int cc = 0; cc < 2; cc++) {
        u64 a[32];
        {
            const u64* bp = (const u64*)(psm + POFF_BP0 + cc * 64);
#pragma unroll
            for (int p = 0; p < 32; p++) a[p] = bp[p];
        }
#pragma unroll 4
        for (int i = 0; i < 64; i++) {
            u64 dd = pk2(dec[i], dec[i]);
            const ulonglong2* wr =
                (const ulonglong2*)(psm + POFF_WP0 + i*128 + cc*64);
#pragma unroll
            for (int j2 = 0; j2 < 16; j2++) {
                ulonglong2 w = wr[j2];
                a[2*j2]   = f2fma(dd, w.x, a[2*j2]);
                a[2*j2+1] = f2fma(dd, w.y, a[2*j2+1]);
            }
        }
#pragma unroll
        for (int p = 0; p < 32; p++) {
            float x, y; upk2(a[p], x, y);
            float g0 = gelu_f(x), g1 = gelu_f(y);
            int jj = cc * 64 + 2 * p;
            o0 = fmaf(g0, psm[POFF_WP1 + jj*3 + 0], o0);
            o1 = fmaf(g0, psm[POFF_WP1 + jj*3 + 1], o1);
            o2 = fmaf(g0, psm[POFF_WP1 + jj*3 + 2], o2);
            o0 = fmaf(g1, psm[POFF_WP1 + jj*3 + 3], o0);
            o1 = fmaf(g1, psm[POFF_WP1 + jj*3 + 4], o1);
            o2 = fmaf(g1, psm[POFF_WP1 + jj*3 + 5], o2);
        }
    }

    atomicAdd(out + row*3 + 0, o0);
    atomicAdd(out + row*3 + 1, o1);
    atomicAdd(out + row*3 + 2, o2);
}

extern "C" void kernel_launch(void* const* d_in, const int* in_sizes, int n_in,
                              void* d_out, int out_size) {
    const float* lat  = (const float*)d_in[0];
    const float* rnd  = (const float*)d_in[1];
    const float* qry  = (const float*)d_in[2];
    const float* we0  = (const float*)d_in[3];
    const float* be0  = (const float*)d_in[4];
    const float* we1  = (const float*)d_in[5];
    const float* be1  = (const float*)d_in[6];
    const float* we2  = (const float*)d_in[7];
    const float* be2  = (const float*)d_in[8];
    const float* wsw0 = (const float*)d_in[9];
    const float* bsw0 = (const float*)d_in[10];
    const float* wsw1 = (const float*)d_in[11];
    const float* bsw1 = (const float*)d_in[12];
    const float* wp0  = (const float*)d_in[13];
    const float* bp0  = (const float*)d_in[14];
    const float* wp1  = (const float*)d_in[15];
    const float* bp1  = (const float*)d_in[16];
    float* out = (float*)d_out;

    cudaFuncSetAttribute(magno_kernel, cudaFuncAttributeMaxDynamicSharedMemorySize, SMEM_BYTES);
    cudaFuncSetAttribute(proj_kernel,  cudaFuncAttributeMaxDynamicSharedMemorySize, PSMEM_BYTES);
    zero_out_kernel<<<(NB*NQ*COUT + 255)/256, 256>>>(out);
    setup_kernel<<<1, 1024>>>(lat);
    magno_kernel<<<NBLOCK, THREADS, SMEM_BYTES>>>(
        lat, rnd, qry, we0, be0, we1, be1, we2, be2,
        wsw0, bsw0, wsw1, bsw1);
    proj_kernel<<<PGRID, PTHREADS, PSMEM_BYTES>>>(wp0, bp0, wp1, bp1, out);
}

// round 17
// speedup vs baseline: 1.5030x; 1.0418x over previous
#include <cuda_runtime.h>
#include <cuda_bf16.h>
#include <math.h>
#include <cstdint>

#define FULLMASK 0xffffffffu
typedef unsigned long long u64;

static constexpr int NL     = 2048;
static constexpr int NQ     = 16384;
static constexpr int NB     = 2;
static constexpr int H      = 64;
static constexpr int PH     = 256;
static constexpr int COUT   = 3;
static constexpr int KCAP   = 32;
static constexpr int CAP    = 160;
static constexpr int THREADS= 128;
static constexpr int WARPS  = 4;
static constexpr int NBLOCK = 444;   // 148 SMs x 3 CTAs
static constexpr int GRIDW  = 9;     // 9x9 cells; 1/9 > 0.11 radius
static constexpr int NCELL  = GRIDW * GRIDW;

// device scratch
__device__ float  g_dec[NB * NQ * H];     // 8 MB
__device__ int    g_cellstart[NCELL + 1];
__device__ float4 g_spack[NL];            // {x, y, bitcast(idx), 0}

// ---- main-kernel SMEM byte offsets ----
static constexpr int OFF_ASTG  = 0;       // 4 warps x 4096 (A staging)         = 16384
static constexpr int OFF_FRAGB = 16384;   // 4 arrays x 1024 u64 (B fragments)  = 32768
static constexpr int OFF_CAND  = 49152;   // 4 warps x 160 u64                  = 5120
static constexpr int OFF_WE0   = 54272;   // 256 f32
static constexpr int OFF_BE0   = 55296;   // 64 f32
static constexpr int OFF_BE1   = 55552;
static constexpr int OFF_BE2   = 55808;
static constexpr int OFF_WSW0  = 56064;
static constexpr int OFF_BSW0  = 56192;
static constexpr int OFF_WSW1  = 56256;
static constexpr int OFF_BSW1  = 56384;   // 2 f32
static constexpr int OFF_CS    = 56448;   // 82 ints = 328 B
static constexpr int SMEM_BYTES= 56832;   // x3 CTAs = 166.5KB; L1D ~57KB

// ---------- helpers ----------
__device__ __forceinline__ uint32_t smem_to_u32(const void* p) {
    uint32_t a;
    asm("{ .reg .u64 t; cvta.to.shared.u64 t, %1; cvt.u32.u64 %0, t; }" : "=r"(a) : "l"(p));
    return a;
}
__device__ __forceinline__ uint32_t pkbf(float lo, float hi) {
    uint32_t r; asm("cvt.rn.bf16x2.f32 %0, %1, %2;" : "=r"(r) : "f"(hi), "f"(lo)); return r;
}
__device__ __forceinline__ float lof(float x) {
    return x - __bfloat162float(__float2bfloat16(x));
}
__device__ __forceinline__ void hmma(float c[4], const uint32_t a[4], uint32_t b0, uint32_t b1) {
    asm volatile("mma.sync.aligned.m16n8k16.row.col.f32.bf16.bf16.f32 "
        "{%0,%1,%2,%3}, {%4,%5,%6,%7}, {%8,%9}, {%0,%1,%2,%3};"
        : "+f"(c[0]), "+f"(c[1]), "+f"(c[2]), "+f"(c[3])
        : "r"(a[0]), "r"(a[1]), "r"(a[2]), "r"(a[3]), "r"(b0), "r"(b1));
}
__device__ __forceinline__ void ldsm4(uint32_t r[4], uint32_t addr) {
    asm volatile("ldmatrix.sync.aligned.m8n8.x4.shared.b16 {%0,%1,%2,%3}, [%4];"
        : "=r"(r[0]), "=r"(r[1]), "=r"(r[2]), "=r"(r[3]) : "r"(addr));
}
__device__ __forceinline__ u64 pk2(float a, float b) {
    u64 r; asm("mov.b64 %0,{%1,%2};" : "=l"(r) : "f"(a), "f"(b)); return r;
}
__device__ __forceinline__ void upk2(u64 v, float& a, float& b) {
    asm("mov.b64 {%0,%1},%2;" : "=f"(a), "=f"(b) : "l"(v));
}
__device__ __forceinline__ u64 f2fma(u64 a, u64 b, u64 c) {
    u64 d; asm("fma.rn.f32x2 %0,%1,%2,%3;" : "=l"(d) : "l"(a), "l"(b), "l"(c)); return d;
}
__device__ __forceinline__ u64 f2add(u64 a, u64 b) {
    u64 d; asm("add.rn.f32x2 %0,%1,%2;" : "=l"(d) : "l"(a), "l"(b)); return d;
}
__device__ __forceinline__ unsigned redux_min_u32(unsigned v) {
    unsigned r; asm("redux.sync.min.u32 %0, %1, 0xffffffff;" : "=r"(r) : "r"(v)); return r;
}
__device__ __forceinline__ float gelu_f(float x) {
    float z = fabsf(x) * 0.7071067811865476f;
    float t = __fdividef(1.0f, fmaf(0.3275911f, z, 1.0f));
    float p = t * fmaf(t, fmaf(t, fmaf(t, fmaf(t, 1.061405429f, -1.453152027f),
                                        1.421413741f), -0.284496736f), 0.254829592f);
    float e = __expf(-z * z);
    float er = fmaf(-p, e, 1.0f);
    er = copysignf(er, x);
    return 0.5f * x * (1.0f + er);
}
__device__ __forceinline__ void ce(u64& a, u64& b) {
    u64 lo = a < b ? a : b;
    u64 hi = a < b ? b : a;
    a = lo; b = hi;
}
__device__ __forceinline__ int cell_of(float x) {
    int c = (int)(x * (float)GRIDW);
    return c < 0 ? 0 : (c > GRIDW-1 ? GRIDW-1 : c);
}

// ======== fused setup: bin + prefix + scatter (output-deterministic) ========
__global__ void __launch_bounds__(1024)
setup_kernel(const float* __restrict__ lat) {
    __shared__ int scnt[NCELL];
    __shared__ int soff[NCELL];
    __shared__ int sstart[NCELL + 1];
    const int tid = threadIdx.x;
    if (tid < NCELL) scnt[tid] = 0;
    __syncthreads();

    float x0 = lat[2*tid],        y0 = lat[2*tid+1];
    float x1 = lat[2*(tid+1024)], y1 = lat[2*(tid+1024)+1];
    int c0 = cell_of(y0) * GRIDW + cell_of(x0);
    int c1 = cell_of(y1) * GRIDW + cell_of(x1);
    atomicAdd(&scnt[c0], 1);
    atomicAdd(&scnt[c1], 1);
    __syncthreads();

    if (tid == 0) {
        int s = 0;
#pragma unroll 1
        for (int c = 0; c < NCELL; c++) {
            sstart[c] = s;
            soff[c]   = s;
            s += scnt[c];
        }
        sstart[NCELL] = s;
    }
    __syncthreads();

    if (tid < NCELL + 1) g_cellstart[tid] = sstart[tid];

    int p0 = atomicAdd(&soff[c0], 1);
    g_spack[p0] = make_float4(x0, y0, __int_as_float(tid), 0.0f);
    int p1 = atomicAdd(&soff[c1], 1);
    g_spack[p1] = make_float4(x1, y1, __int_as_float(tid + 1024), 0.0f);
}

__global__ void __launch_bounds__(THREADS, 3)
magno_kernel(const float* __restrict__ lat,  const float* __restrict__ rnd,
             const float* __restrict__ qry,
             const float* __restrict__ we0,  const float* __restrict__ be0,
             const float* __restrict__ we1,  const float* __restrict__ be1,
             const float* __restrict__ we2,  const float* __restrict__ be2,
             const float* __restrict__ wsw0, const float* __restrict__ bsw0,
             const float* __restrict__ wsw1, const float* __restrict__ bsw1)
{
    extern __shared__ char smem[];
    const uint32_t smem_base = smem_to_u32(smem);
    const int tid = threadIdx.x, warp = tid >> 5, lane = tid & 31;

    // ---- B fragments: arrays 0=W1hi 1=W1lo 2=W2hi 3=W2lo ----
    {
        u64* fbw = (u64*)(smem + OFF_FRAGB);
        for (int i = tid; i < 4096; i += THREADS) {
            int arr = i >> 10, rem = i & 1023;
            int frag = rem >> 5, l = rem & 31;
            int kt = frag >> 3, nt = frag & 7;
            int k0 = kt*16 + 2*(l & 3);
            int n  = nt*8 + (l >> 2);
            const float* W = (arr < 2) ? we1 : we2;
            float w00 = W[(k0  )*H + n], w01 = W[(k0+1)*H + n];
            float w10 = W[(k0+8)*H + n], w11 = W[(k0+9)*H + n];
            if (arr & 1) { w00 = lof(w00); w01 = lof(w01); w10 = lof(w10); w11 = lof(w11); }
            fbw[i] = (u64)pkbf(w00, w01) | ((u64)pkbf(w10, w11) << 32);
        }
    }
    {
        float* f = (float*)smem;
        for (int t = tid; t < 4*H; t += THREADS) f[OFF_WE0/4 + t] = we0[t];
        for (int t = tid; t < H;   t += THREADS) {
            f[OFF_BE0/4 + t] = be0[t];
            f[OFF_BE1/4 + t] = be1[t];
            f[OFF_BE2/4 + t] = be2[t];
        }
        if (tid < 32)              f[OFF_WSW0/4 + tid]    = wsw0[tid];
        if (tid < 16)              f[OFF_BSW0/4 + tid]    = bsw0[tid];
        if (tid >= 32 && tid < 64) f[OFF_WSW1/4 + tid-32] = wsw1[tid-32];
        if (tid >= 64 && tid < 66) f[OFF_BSW1/4 + tid-64] = bsw1[tid-64];
        int* cs = (int*)(smem + OFF_CS);
        for (int t = tid; t < NCELL+1; t += THREADS) cs[t] = g_cellstart[t];
    }
    __syncthreads();

    u64* cand = (u64*)(smem + OFF_CAND) + warp * CAP;
    const u64* fb = (const u64*)(smem + OFF_FRAGB);
    const int* cs = (const int*)(smem + OFF_CS);
    const float2* latf2 = (const float2*)lat;
    const float* smf = (const float*)smem;
    char* astg = smem + OFF_ASTG + warp * 4096;
    const uint32_t astg_u32 = smem_base + OFF_ASTG + warp * 4096;

    const float R0SQ = (float)(0.055 * 0.055);
    const float R1SQ = (float)(0.11  * 0.11);
    const unsigned lt_mask = (1u << lane) - 1u;

    for (int q = blockIdx.x * WARPS + warp; q < NB * NQ; q += gridDim.x * WARPS) {
        const int  bix = q >> 14;
        const float qx = qry[2*q], qy = qry[2*q+1];

        // ---- scale-mixing weights ----
        float s0 = smf[OFF_BSW1/4+0], s1 = smf[OFF_BSW1/4+1];
#pragma unroll
        for (int t = 0; t < 16; t++) {
            float z = smf[OFF_BSW0/4+t] + qx*smf[OFF_WSW0/4+t] + qy*smf[OFF_WSW0/4+16+t];
            z = fmaxf(z, 0.0f);
            s0 = fmaf(z, smf[OFF_WSW1/4+2*t+0], s0);
            s1 = fmaf(z, smf[OFF_WSW1/4+2*t+1], s1);
        }
        float mx = fmaxf(s0, s1);
        float e0 = __expf(s0 - mx), e1 = __expf(s1 - mx);
        float inv = __fdividef(1.0f, e0 + e1);
        float sw0v = e0 * inv, sw1v = e1 * inv;

        // ---- candidate collection via 9x9 grid ----
        int cnt = 0;
        {
            const int qcx = cell_of(qx), qcy = cell_of(qy);
            const int rx0 = qcx > 0 ? qcx-1 : 0;
            const int rx1 = qcx < GRIDW-1 ? qcx+1 : GRIDW-1;
            const int ry0 = qcy > 0 ? qcy-1 : 0;
            const int ry1 = qcy < GRIDW-1 ? qcy+1 : GRIDW-1;
#pragma unroll 1
            for (int ry = ry0; ry <= ry1; ry++) {
                int beg = cs[ry*GRIDW + rx0];
                int end = cs[ry*GRIDW + rx1 + 1];
#pragma unroll 1
                for (int t0 = beg; t0 < end; t0 += 32) {
                    int p = t0 + lane;
                    bool pr = false;
                    float d2 = 0.0f;
                    unsigned idx = 0;
                    if (p < end) {
                        float4 sp = __ldg(g_spack + p);
                        float dx = qx - sp.x, dy = qy - sp.y;
                        d2 = __fadd_rn(__fmul_rn(dx, dx), __fmul_rn(dy, dy));
                        idx = (unsigned)__float_as_int(sp.z);
                        pr = d2 <= R1SQ;
                    }
                    unsigned m = __ballot_sync(FULLMASK, pr);
                    if (pr) {
                        int pos = cnt + __popc(m & lt_mask);
                        if (pos < CAP)
                            cand[pos] = ((u64)__float_as_uint(d2) << 32) | idx;
                    }
                    cnt += __popc(m);
                }
            }
        }
        if (cnt > CAP) cnt = CAP;
        __syncwarp();

        // ---- exact K=32 selection ----
        u64 mykey = 0x7f7fffff00000000ull;
        int nsel;
        if (cnt <= KCAP) {
            nsel = cnt;
            if (lane < cnt) mykey = cand[lane];
        } else {
            nsel = KCAP;
            u64 c0, c1, c2, c3, c4, c5;
            c0 = (lane       < cnt) ? cand[lane      ] : ~0ull;
            c1 = (lane + 32  < cnt) ? cand[lane + 32 ] : ~0ull;
            c2 = (lane + 64  < cnt) ? cand[lane + 64 ] : ~0ull;
            c3 = (lane + 96  < cnt) ? cand[lane + 96 ] : ~0ull;
            c4 = (lane + 128 < cnt) ? cand[lane + 128] : ~0ull;
            c5 = ~0ull;
            ce(c0,c1); ce(c2,c3); ce(c4,c5);
            ce(c0,c2); ce(c3,c5); ce(c1,c4);
            ce(c0,c1); ce(c2,c3); ce(c4,c5);
            ce(c1,c2); ce(c3,c4); ce(c2,c3);
            unsigned hdb = (unsigned)(c0 >> 32);
#pragma unroll 1
            for (int r = 0; r < KCAP; r++) {
                unsigned m = redux_min_u32(hdb);
                unsigned tied = __ballot_sync(FULLMASK, hdb == m);
                int src;
                if ((tied & (tied - 1u)) == 0u) {
                    src = __ffs(tied) - 1;
                } else {
                    unsigned lw = (hdb == m) ? (unsigned)c0 : 0xffffffffu;
                    unsigned mi = redux_min_u32(lw);
                    src = __ffs(__ballot_sync(FULLMASK, lw == mi)) - 1;
                }
                u64 win = __shfl_sync(FULLMASK, c0, src);
                if (lane == r) mykey = win;
                bool pop = (lane == src);
                c0 = pop ? c1 : c0; c1 = pop ? c2 : c1; c2 = pop ? c3 : c2;
                c3 = pop ? c4 : c3; c4 = pop ? c5 : c4; c5 = pop ? ~0ull : c5;
                hdb = (unsigned)(c0 >> 32);
            }
        }
        float seld2  = __uint_as_float((unsigned)(mykey >> 32));
        int   selidx = (int)(mykey & 0xffffffffu);
        if (lane >= nsel) { seld2 = 3.4e38f; selidx = 0; }

        bool v0 = (lane < nsel) && (seld2 <= R0SQ);
        int  c0cnt = __popc(__ballot_sync(FULLMASK, v0));
        float coeff = 0.0f;
        if (v0)          coeff += sw0v / (float)(c0cnt > 1 ? c0cnt : 1);
        if (lane < nsel) coeff += sw1v / (float)(nsel  > 1 ? nsel  : 1);

        {
            const float* frowf = rnd + (size_t)(bix * NL + selidx) * H;
            asm volatile("prefetch.global.L1 [%0];" :: "l"(frowf));
            asm volatile("prefetch.global.L1 [%0];" :: "l"(frowf + 32));
        }

        // ---- layer 0 (lane = neighbor row), pack bf16 hi/lo ----
        uint32_t hiP[32], loP[32];
        {
            float2 yc = __ldg(latf2 + selidx);
            u64 yx2 = pk2(yc.x, yc.x), yy2 = pk2(yc.y, yc.y);
            u64 qx2 = pk2(qx, qx),     qy2 = pk2(qy, qy);
            const u64* w0r0 = (const u64*)(smem + OFF_WE0);
            const u64* w0r1 = (const u64*)(smem + OFF_WE0 + 256);
            const u64* w0r2 = (const u64*)(smem + OFF_WE0 + 512);
            const u64* w0r3 = (const u64*)(smem + OFF_WE0 + 768);
            const u64* b0p  = (const u64*)(smem + OFF_BE0);
#pragma unroll
            for (int jp = 0; jp < 32; jp++) {
                u64 t = b0p[jp];
                t = f2fma(yx2, w0r0[jp], t);
                t = f2fma(yy2, w0r1[jp], t);
                t = f2fma(qx2, w0r2[jp], t);
                t = f2fma(qy2, w0r3[jp], t);
                float a, b; upk2(t, a, b);
                float g0 = gelu_f(a), g1 = gelu_f(b);
                hiP[jp] = pkbf(g0, g1);
                loP[jp] = pkbf(lof(g0), lof(g1));
            }
        }

        // ---- stage hi/lo, ldmatrix A fragments ----
        uint32_t Ahi[2][4][4], Alo[2][4][4];
        __syncwarp();
#pragma unroll
        for (int c = 0; c < 8; c++) {
            uint32_t off = (uint32_t)(lane*128 + ((c ^ (lane & 7)) << 4));
            *(uint4*)(astg + off) = make_uint4(hiP[4*c], hiP[4*c+1], hiP[4*c+2], hiP[4*c+3]);
        }
        __syncwarp();
#pragma unroll
        for (int mt = 0; mt < 2; mt++)
#pragma unroll
            for (int kt = 0; kt < 4; kt++) {
                int row = mt*16 + (lane & 15);
                int chunk = 2*kt + (lane >> 4);
                ldsm4(Ahi[mt][kt], astg_u32 + row*128 + ((chunk ^ (row & 7)) << 4));
            }
        __syncwarp();
#pragma unroll
        for (int c = 0; c < 8; c++) {
            uint32_t off = (uint32_t)(lane*128 + ((c ^ (lane & 7)) << 4));
            *(uint4*)(astg + off) = make_uint4(loP[4*c], loP[4*c+1], loP[4*c+2], loP[4*c+3]);
        }
        __syncwarp();
#pragma unroll
        for (int mt = 0; mt < 2; mt++)
#pragma unroll
            for (int kt = 0; kt < 4; kt++) {
                int row = mt*16 + (lane & 15);
                int chunk = 2*kt + (lane >> 4);
                ldsm4(Alo[mt][kt], astg_u32 + row*128 + ((chunk ^ (row & 7)) << 4));
            }

        // ---- layer 1 ----
        float acc[2][8][4];
#pragma unroll
        for (int mt = 0; mt < 2; mt++)
#pragma unroll
            for (int nt = 0; nt < 8; nt++)
#pragma unroll
                for (int r = 0; r < 4; r++) acc[mt][nt][r] = 0.0f;

#define PASS(AREG, ARR) \
        _Pragma("unroll") \
        for (int kt = 0; kt < 4; kt++) { \
            u64 bf[8]; \
            _Pragma("unroll") \
            for (int nt = 0; nt < 8; nt++) bf[nt] = fb[(ARR)*1024 + (kt*8+nt)*32 + lane]; \
            _Pragma("unroll") \
            for (int mt = 0; mt < 2; mt++) \
            _Pragma("unroll") \
            for (int nt = 0; nt < 8; nt++) \
                hmma(acc[mt][nt], AREG[mt][kt], (uint32_t)bf[nt], (uint32_t)(bf[nt] >> 32)); \
        }

        PASS(Ahi, 0)
        PASS(Alo, 0)
        PASS(Ahi, 1)

        // ---- bias + gelu + re-fragment ----
        uint32_t A2hi[2][4][4], A2lo[2][4][4];
        {
            const float2* b1p = (const float2*)(smem + OFF_BE1);
#pragma unroll
            for (int mt = 0; mt < 2; mt++)
#pragma unroll
                for (int j = 0; j < 4; j++)
#pragma unroll
                    for (int s = 0; s < 2; s++) {
                        int nt = 2*j + s;
                        float2 bb = b1p[nt*4 + (lane & 3)];
                        float g0 = gelu_f(acc[mt][nt][0] + bb.x);
                        float g1 = gelu_f(acc[mt][nt][1] + bb.y);
                        float g2 = gelu_f(acc[mt][nt][2] + bb.x);
                        float g3 = gelu_f(acc[mt][nt][3] + bb.y);
                        A2hi[mt][j][2*s]   = pkbf(g0, g1);
                        A2hi[mt][j][2*s+1] = pkbf(g2, g3);
                        A2lo[mt][j][2*s]   = pkbf(lof(g0), lof(g1));
                        A2lo[mt][j][2*s+1] = pkbf(lof(g2), lof(g3));
                    }
        }

        // ---- layer 2 ----
#pragma unroll
        for (int mt = 0; mt < 2; mt++)
#pragma unroll
            for (int nt = 0; nt < 8; nt++)
#pragma unroll
                for (int r = 0; r < 4; r++) acc[mt][nt][r] = 0.0f;

        PASS(A2hi, 2)
        PASS(A2lo, 2)
        PASS(A2hi, 3)
#undef PASS

        // ---- epilogue in fragment layout ----
        {
            float cf[2][2]; int si[2][2];
#pragma unroll
            for (int mt = 0; mt < 2; mt++)
#pragma unroll
                for (int hf = 0; hf < 2; hf++) {
                    int src = mt*16 + (lane >> 2) + 8*hf;
                    cf[mt][hf] = __shfl_sync(FULLMASK, coeff,  src);
                    si[mt][hf] = __shfl_sync(FULLMASK, selidx, src);
                }
            const float* rb = rnd + (size_t)bix * NL * H;
            const float2* b2p = (const float2*)(smem + OFF_BE2);
            u64 red[8];
#pragma unroll
            for (int nt = 0; nt < 8; nt++) {
                float2 bb = b2p[nt*4 + (lane & 3)];
                int colb = nt*8 + 2*(lane & 3);
                float sx = 0.f, sy = 0.f;
#pragma unroll
                for (int mt = 0; mt < 2; mt++)
#pragma unroll
                    for (int hf = 0; hf < 2; hf++) {
                        float2 fy = __ldg((const float2*)(rb + (size_t)si[mt][hf]*H + colb));
                        float cfv = cf[mt][hf];
                        sx += (acc[mt][nt][2*hf+0] + bb.x) * fy.x * cfv;
                        sy += (acc[mt][nt][2*hf+1] + bb.y) * fy.y * cfv;
                    }
                u64 v = pk2(sx, sy);
                v = f2add(v, __shfl_xor_sync(FULLMASK, v, 4));
                v = f2add(v, __shfl_xor_sync(FULLMASK, v, 8));
                v = f2add(v, __shfl_xor_sync(FULLMASK, v, 16));
                red[nt] = v;
            }
            u64 myd = red[0];
#pragma unroll
            for (int nt = 1; nt < 8; nt++)
                if ((lane >> 2) == nt) myd = red[nt];
            ((u64*)g_dec)[(size_t)q * 32 + lane] = myd;
        }
    }
}

// ======== HMMA projection: [32768x64] @ wp0 -> gelu -> @ wp1, warp = 32 rows ======
static constexpr int PTHREADS = 128;                       // 4 warps
static constexpr int PROWS    = 4 * 32;                    // 128 rows per block
static constexpr int PGRID    = NB * NQ / PROWS;           // 256
// proj SMEM byte offsets
static constexpr int POFF_FB    = 0;        // 2 arrays x 4096 u64 = 65536
static constexpr int POFF_BP0   = 65536;    // 256 f32 = 1024
static constexpr int POFF_WP1P  = 66560;    // 256 x float4 = 4096
static constexpr int POFF_BP1   = 70656;    // 4 f32
static constexpr int POFF_PSTG  = 70672;    // 4 warps x 4096 = 16384
static constexpr int PSMEM_BYTES= 87056;    // -> 2 CTAs/SM

__global__ void __launch_bounds__(PTHREADS)
proj_kernel(const float* __restrict__ wp0, const float* __restrict__ bp0,
            const float* __restrict__ wp1, const float* __restrict__ bp1,
            float* __restrict__ out)
{
    extern __shared__ char psmem[];
    const uint32_t psbase = smem_to_u32(psmem);
    const int tid = threadIdx.x, warp = tid >> 5, lane = tid & 31;

    // ---- B fragments for wp0 (hi/lo), frag (kt 0..3, nt 0..31) ----
    {
        u64* fbw = (u64*)(psmem + POFF_FB);
        for (int i = tid; i < 8192; i += PTHREADS) {
            int arr = i >> 12, rem = i & 4095;
            int frag = rem >> 5, l = rem & 31;
            int kt = frag >> 5, nt = frag & 31;
            int k0 = kt*16 + 2*(l & 3);
            int n  = nt*8 + (l >> 2);
            float w00 = wp0[(size_t)(k0  )*PH + n], w01 = wp0[(size_t)(k0+1)*PH + n];
            float w10 = wp0[(size_t)(k0+8)*PH + n], w11 = wp0[(size_t)(k0+9)*PH + n];
            if (arr) { w00 = lof(w00); w01 = lof(w01); w10 = lof(w10); w11 = lof(w11); }
            fbw[i] = (u64)pkbf(w00, w01) | ((u64)pkbf(w10, w11) << 32);
        }
        float* f = (float*)psmem;
        for (int t = tid; t < PH; t += PTHREADS) f[POFF_BP0/4 + t] = bp0[t];
        for (int t = tid; t < PH; t += PTHREADS) {
            f[POFF_WP1P/4 + 4*t + 0] = wp1[3*t + 0];
            f[POFF_WP1P/4 + 4*t + 1] = wp1[3*t + 1];
            f[POFF_WP1P/4 + 4*t + 2] = wp1[3*t + 2];
            f[POFF_WP1P/4 + 4*t + 3] = 0.0f;
        }
        if (tid < COUT) f[POFF_BP1/4 + tid] = bp1[tid];
    }
    __syncthreads();

    const u64* fb = (const u64*)(psmem + POFF_FB);
    const float2* bp0f2 = (const float2*)(psmem + POFF_BP0);
    const float4* wp1p  = (const float4*)(psmem + POFF_WP1P);
    const float*  bp1s  = (const float*)(psmem + POFF_BP1);
    char* astg = psmem + POFF_PSTG + warp * 4096;
    const uint32_t astg_u32 = psbase + POFF_PSTG + warp * 4096;

    const int rowbase = blockIdx.x * PROWS + warp * 32;

    // ---- load dec row (lane = row), pack bf16 hi/lo ----
    uint32_t hiP[32], loP[32];
    {
        const u64* drow = (const u64*)(g_dec + (size_t)(rowbase + lane) * H);
#pragma unroll
        for (int jp = 0; jp < 32; jp++) {
            float a, b; upk2(drow[jp], a, b);
            hiP[jp] = pkbf(a, b);
            loP[jp] = pkbf(lof(a), lof(b));
        }
    }

    // ---- stage hi/lo, ldmatrix A fragments ----
    uint32_t Ahi[2][4][4], Alo[2][4][4];
    __syncwarp();
#pragma unroll
    for (int c = 0; c < 8; c++) {
        uint32_t off = (uint32_t)(lane*128 + ((c ^ (lane & 7)) << 4));
        *(uint4*)(astg + off) = make_uint4(hiP[4*c], hiP[4*c+1], hiP[4*c+2], hiP[4*c+3]);
    }
    __syncwarp();
#pragma unroll
    for (int mt = 0; mt < 2; mt++)
#pragma unroll
        for (int kt = 0; kt < 4; kt++) {
            int row = mt*16 + (lane & 15);
            int chunk = 2*kt + (lane >> 4);
            ldsm4(Ahi[mt][kt], astg_u32 + row*128 + ((chunk ^ (row & 7)) << 4));
        }
    __syncwarp();
#pragma unroll
    for (int c = 0; c < 8; c++) {
        uint32_t off = (uint32_t)(lane*128 + ((c ^ (lane & 7)) << 4));
        *(uint4*)(astg + off) = make_uint4(loP[4*c], loP[4*c+1], loP[4*c+2], loP[4*c+3]);
    }
    __syncwarp();
#pragma unroll
    for (int mt = 0; mt < 2; mt++)
#pragma unroll
        for (int kt = 0; kt < 4; kt++) {
            int row = mt*16 + (lane & 15);
            int chunk = 2*kt + (lane >> 4);
            ldsm4(Alo[mt][kt], astg_u32 + row*128 + ((chunk ^ (row & 7)) << 4));
        }

    // ---- per-lane output partials: rows rr = mt*2+hf -> mt*16 + hf*8 + (lane>>2) ----
    float oacc[4][3];
#pragma unroll
    for (int rr = 0; rr < 4; rr++)
#pragma unroll
        for (int k = 0; k < 3; k++) oacc[rr][k] = 0.0f;

#pragma unroll 1
    for (int ch = 0; ch < 4; ch++) {           // nt chunks of 8 (N = 256)
        float acc[2][8][4];
#pragma unroll
        for (int mt = 0; mt < 2; mt++)
#pragma unroll
            for (int nt = 0; nt < 8; nt++)
#pragma unroll
                for (int r = 0; r < 4; r++) acc[mt][nt][r] = 0.0f;

#pragma unroll
        for (int kt = 0; kt < 4; kt++) {
            u64 bh[8], bl[8];
#pragma unroll
            for (int nt = 0; nt < 8; nt++) {
                int fi = (kt*32 + ch*8 + nt)*32 + lane;
                bh[nt] = fb[fi];
                bl[nt] = fb[4096 + fi];
            }
#pragma unroll
            for (int mt = 0; mt < 2; mt++)
#pragma unroll
                for (int nt = 0; nt < 8; nt++) {
                    hmma(acc[mt][nt], Ahi[mt][kt], (uint32_t)bh[nt], (uint32_t)(bh[nt] >> 32));
                    hmma(acc[mt][nt], Alo[mt][kt], (uint32_t)bh[nt], (uint32_t)(bh[nt] >> 32));
                    hmma(acc[mt][nt], Ahi[mt][kt], (uint32_t)bl[nt], (uint32_t)(bl[nt] >> 32));
                }
        }

        // bias + gelu + second layer accumulate (fragment layout)
#pragma unroll
        for (int nt = 0; nt < 8; nt++) {
            int ntg = ch*8 + nt;
            float2 bb = bp0f2[ntg*4 + (lane & 3)];
            int col0 = ntg*8 + 2*(lane & 3);
            float4 w0v = wp1p[col0];
            float4 w1v = wp1p[col0 + 1];
#pragma unroll
            for (int mt = 0; mt < 2; mt++) {
                float g0 = gelu_f(acc[mt][nt][0] + bb.x);
                float g1 = gelu_f(acc[mt][nt][1] + bb.y);
                float g2 = gelu_f(acc[mt][nt][2] + bb.x);
                float g3 = gelu_f(acc[mt][nt][3] + bb.y);
                oacc[mt*2+0][0] = fmaf(g0, w0v.x, fmaf(g1, w1v.x, oacc[mt*2+0][0]));
                oacc[mt*2+0][1] = fmaf(g0, w0v.y, fmaf(g1, w1v.y, oacc[mt*2+0][1]));
                oacc[mt*2+0][2] = fmaf(g0, w0v.z, fmaf(g1, w1v.z, oacc[mt*2+0][2]));
                oacc[mt*2+1][0] = fmaf(g2, w0v.x, fmaf(g3, w1v.x, oacc[mt*2+1][0]));
                oacc[mt*2+1][1] = fmaf(g2, w0v.y, fmaf(g3, w1v.y, oacc[mt*2+1][1]));
                oacc[mt*2+1][2] = fmaf(g2, w0v.z, fmaf(g3, w1v.z, oacc[mt*2+1][2]));
            }
        }
    }

    // ---- reduce across the 4 lanes sharing each row (xor 1, 2) ----
#pragma unroll
    for (int rr = 0; rr < 4; rr++) {
        u64 v01 = pk2(oacc[rr][0], oacc[rr][1]);
        float v2 = oacc[rr][2];
        v01 = f2add(v01, __shfl_xor_sync(FULLMASK, v01, 1));
        v2 += __shfl_xor_sync(FULLMASK, v2, 1);
        v01 = f2add(v01, __shfl_xor_sync(FULLMASK, v01, 2));
        v2 += __shfl_xor_sync(FULLMASK, v2, 2);
        float a, b; upk2(v01, a, b);
        oacc[rr][0] = a; oacc[rr][1] = b; oacc[rr][2] = v2;
    }
    if ((lane & 3) == 0) {
        float b0v = bp1s[0], b1v = bp1s[1], b2v = bp1s[2];
#pragma unroll
        for (int rr = 0; rr < 4; rr++) {
            int mt = rr >> 1, hf = rr & 1;
            int row = rowbase + mt*16 + hf*8 + (lane >> 2);
            out[row*3 + 0] = oacc[rr][0] + b0v;
            out[row*3 + 1] = oacc[rr][1] + b1v;
            out[row*3 + 2] = oacc[rr][2] + b2v;
        }
    }
}

extern "C" void kernel_launch(void* const* d_in, const int* in_sizes, int n_in,
                              void* d_out, int out_size) {
    const float* lat  = (const float*)d_in[0];
    const float* rnd  = (const float*)d_in[1];
    const float* qry  = (const float*)d_in[2];
    const float* we0  = (const float*)d_in[3];
    const float* be0  = (const float*)d_in[4];
    const float* we1  = (const float*)d_in[5];
    const float* be1  = (const float*)d_in[6];
    const float* we2  = (const float*)d_in[7];
    const float* be2  = (const float*)d_in[8];
    const float* wsw0 = (const float*)d_in[9];
    const float* bsw0 = (const float*)d_in[10];
    const float* wsw1 = (const float*)d_in[11];
    const float* bsw1 = (const float*)d_in[12];
    const float* wp0  = (const float*)d_in[13];
    const float* bp0  = (const float*)d_in[14];
    const float* wp1  = (const float*)d_in[15];
    const float* bp1  = (const float*)d_in[16];
    float* out = (float*)d_out;

    cudaFuncSetAttribute(magno_kernel, cudaFuncAttributeMaxDynamicSharedMemorySize, SMEM_BYTES);
    cudaFuncSetAttribute(proj_kernel,  cudaFuncAttributeMaxDynamicSharedMemorySize, PSMEM_BYTES);
    setup_kernel<<<1, 1024>>>(lat);
    magno_kernel<<<NBLOCK, THREADS, SMEM_BYTES>>>(
        lat, rnd, qry, we0, be0, we1, be1, we2, be2,
        wsw0, bsw0, wsw1, bsw1);
    proj_kernel<<<PGRID, PTHREADS, PSMEM_BYTES>>>(wp0, bp0, wp1, bp1, out);
}